// round 1
// baseline (speedup 1.0000x reference)
#include <cuda_runtime.h>
#include <cstdint>

#define N_SPOT 30000
#define N_USER 30000
#define NE     600000
#define SPLIT  5
#define ATT_IN 512
#define HEADS  4
#define PER    128
#define HID    256

// ---------------- scratch (device globals; no allocation) ----------------
__device__ float g_wq[HEADS * ATT_IN];                       // W_att @ q_att per head
__device__ float g_Y[(size_t)HEADS * N_SPOT * ATT_IN];       // attention-weighted x per head
__device__ float g_xs[(size_t)N_SPOT * ATT_IN];              // attention output (512-d)
__device__ float g_tmp_u[(size_t)N_USER * HID];              // xu @ W (messages from users)
__device__ float g_tmp_s[(size_t)N_SPOT * HID];              // xs @ W (messages from spots)
__device__ float g_hs0[(size_t)N_SPOT * HID];
__device__ float g_hs1[(size_t)N_SPOT * HID];
__device__ float g_hu0[(size_t)N_USER * HID];
__device__ float g_hu1[(size_t)N_USER * HID];
__device__ float g_acc_s[(size_t)N_SPOT * HID];
__device__ float g_acc_u[(size_t)N_USER * HID];
__device__ float g_inv_us[NE];
__device__ float g_inv_su[NE];
__device__ float g_deg[4 * N_SPOT];  // [us_src(user), us_dst(spot), su_src(spot), su_dst(user)]

// ---------------- degree / normalization ----------------
__global__ void deg_count_kernel(const int* __restrict__ idx, float* __restrict__ deg, int n) {
    int i = blockIdx.x * blockDim.x + threadIdx.x;
    if (i < n) atomicAdd(&deg[idx[i]], 1.0f);
}

__global__ void inv_div_kernel(const int* __restrict__ src, const int* __restrict__ dst,
                               const float* __restrict__ deg_s, const float* __restrict__ deg_d,
                               float* __restrict__ inv, int n) {
    int e = blockIdx.x * blockDim.x + threadIdx.x;
    if (e < n) inv[e] = rsqrtf(deg_s[src[e]] * deg_d[dst[e]]);
}

// ---------------- attention ----------------
__global__ void wq_kernel(const float* __restrict__ W, const float* __restrict__ q,
                          float* __restrict__ wq) {
    int t = blockIdx.x * blockDim.x + threadIdx.x;
    if (t >= HEADS * ATT_IN) return;
    int h = t / ATT_IN, i = t % ATT_IN;
    const float* w = W + ((size_t)h * ATT_IN + i) * PER;
    const float* qq = q + h * PER;
    float s = 0.f;
#pragma unroll 8
    for (int p = 0; p < PER; p++) s += w[p] * qq[p];
    wq[t] = s;
}

// one block (128 thr) per node: logits (via wq), leaky_relu, softmax over SPLIT,
// then Y[h,n,:] = sum_s att * x[n,s,:]
__global__ __launch_bounds__(128) void att_kernel(const float* __restrict__ x,
                                                  const float* __restrict__ wq,
                                                  float* __restrict__ Y) {
    int n = blockIdx.x;
    __shared__ float sx[SPLIT * ATT_IN];
    __shared__ float satt[HEADS][SPLIT];
    const float* xr = x + (size_t)n * (SPLIT * ATT_IN);
    for (int i = threadIdx.x; i < SPLIT * ATT_IN; i += 128) sx[i] = xr[i];
    __syncthreads();

    int w = threadIdx.x >> 5, lane = threadIdx.x & 31;
    if (w < HEADS) {
        float lg[SPLIT];
#pragma unroll
        for (int s = 0; s < SPLIT; s++) {
            float p = 0.f;
            for (int i = lane; i < ATT_IN; i += 32) p += sx[s * ATT_IN + i] * wq[w * ATT_IN + i];
#pragma unroll
            for (int o = 16; o; o >>= 1) p += __shfl_down_sync(0xffffffffu, p, o);
            lg[s] = p;
        }
        if (lane == 0) {
            float mx = -1e30f;
#pragma unroll
            for (int s = 0; s < SPLIT; s++) {
                lg[s] = lg[s] >= 0.f ? lg[s] : 0.2f * lg[s];  // leaky_relu(0.2)
                mx = fmaxf(mx, lg[s]);
            }
            float sum = 0.f;
#pragma unroll
            for (int s = 0; s < SPLIT; s++) { lg[s] = expf(lg[s] - mx); sum += lg[s]; }
            float r = 1.f / sum;
#pragma unroll
            for (int s = 0; s < SPLIT; s++) satt[w][s] = lg[s] * r;
        }
    }
    __syncthreads();

#pragma unroll
    for (int h = 0; h < HEADS; h++) {
        float a0 = satt[h][0], a1 = satt[h][1], a2 = satt[h][2], a3 = satt[h][3], a4 = satt[h][4];
        for (int i = threadIdx.x; i < ATT_IN; i += 128) {
            float y = a0 * sx[i] + a1 * sx[ATT_IN + i] + a2 * sx[2 * ATT_IN + i]
                    + a3 * sx[3 * ATT_IN + i] + a4 * sx[4 * ATT_IN + i];
            Y[((size_t)h * N_SPOT + n) * ATT_IN + i] = y;
        }
    }
}

// ---------------- generic fp32 GEMM: C[M,N] = A[M,K] @ B[K,N] ----------------
// 64x64 tile, TK=16, 256 threads, 4x4 per thread. N multiple of 64, K multiple of 16.
__global__ __launch_bounds__(256) void sgemm_kernel(const float* __restrict__ A, int lda,
                                                    const float* __restrict__ B, int ldb,
                                                    float* __restrict__ C, int ldc,
                                                    int M, int K) {
    __shared__ float As[16][68];
    __shared__ float Bs[16][64];
    const int tid = threadIdx.x;
    const int tx = tid & 15, ty = tid >> 4;
    const int m0 = blockIdx.x * 64, n0 = blockIdx.y * 64;
    const int arow = tid >> 2;
    const int acol = (tid & 3) << 2;
    const int brow = tid >> 4;
    const int bcol = (tid & 15) << 2;
    const bool aval = (m0 + arow) < M;
    const float* Aptr = A + (size_t)(m0 + arow) * lda + acol;
    const float* Bptr = B + (size_t)brow * ldb + n0 + bcol;

    float acc[4][4] = {};
    for (int k0 = 0; k0 < K; k0 += 16) {
        float4 av = make_float4(0.f, 0.f, 0.f, 0.f);
        if (aval) av = *(const float4*)(Aptr + k0);
        float4 bv = *(const float4*)(Bptr + (size_t)k0 * ldb);
        As[acol + 0][arow] = av.x;
        As[acol + 1][arow] = av.y;
        As[acol + 2][arow] = av.z;
        As[acol + 3][arow] = av.w;
        *(float4*)&Bs[brow][bcol] = bv;
        __syncthreads();
#pragma unroll
        for (int k = 0; k < 16; k++) {
            float4 a = *(const float4*)&As[k][ty << 2];
            float4 b = *(const float4*)&Bs[k][tx << 2];
            acc[0][0] += a.x * b.x; acc[0][1] += a.x * b.y; acc[0][2] += a.x * b.z; acc[0][3] += a.x * b.w;
            acc[1][0] += a.y * b.x; acc[1][1] += a.y * b.y; acc[1][2] += a.y * b.z; acc[1][3] += a.y * b.w;
            acc[2][0] += a.z * b.x; acc[2][1] += a.z * b.y; acc[2][2] += a.z * b.z; acc[2][3] += a.z * b.w;
            acc[3][0] += a.w * b.x; acc[3][1] += a.w * b.y; acc[3][2] += a.w * b.z; acc[3][3] += a.w * b.w;
        }
        __syncthreads();
    }
#pragma unroll
    for (int i = 0; i < 4; i++) {
        int m = m0 + (ty << 2) + i;
        if (m < M) {
            float4 v = make_float4(acc[i][0], acc[i][1], acc[i][2], acc[i][3]);
            *(float4*)(C + (size_t)m * ldc + n0 + (tx << 2)) = v;
        }
    }
}

// ---------------- edge scatter: out[dst] += msg[src] * inv_div ----------------
__global__ void scatter_kernel(const float* __restrict__ msg, const int* __restrict__ src,
                               const int* __restrict__ dst, const float* __restrict__ invd,
                               float* __restrict__ out, int n) {
    int idx = blockIdx.x * blockDim.x + threadIdx.x;
    int e = idx >> 6;       // 64 float4 chunks per edge (HID=256)
    int c = idx & 63;
    if (e >= n) return;
    int s = src[e], d = dst[e];
    float sc = invd[e];
    float4 v = ((const float4*)msg)[(size_t)s * 64 + c];
    float* o = out + (size_t)d * HID + c * 4;
    atomicAdd(o + 0, v.x * sc);
    atomicAdd(o + 1, v.y * sc);
    atomicAdd(o + 2, v.z * sc);
    atomicAdd(o + 3, v.w * sc);
}

__global__ void relu_acc_kernel(float* __restrict__ h, float* __restrict__ acc, int n) {
    int i = blockIdx.x * blockDim.x + threadIdx.x;
    if (i < n) {
        float v = h[i];
        v = v > 0.f ? v : 0.f;
        h[i] = v;
        acc[i] += v;
    }
}

// ---------------- outputs ----------------
__global__ void mean_kernel(const float* __restrict__ acc_s, const float* __restrict__ acc_u,
                            float* __restrict__ out, int n) {
    int i = blockIdx.x * blockDim.x + threadIdx.x;
    if (i < n) {
        const float r = 1.f / 3.f;
        out[i] = acc_s[i] * r;
        out[n + i] = acc_u[i] * r;
    }
}

__global__ void out_head_kernel(const float* __restrict__ hs, const float* __restrict__ hu,
                                const float* __restrict__ Ws, const float* __restrict__ bs,
                                const float* __restrict__ Wu, const float* __restrict__ bu,
                                float* __restrict__ out_s, float* __restrict__ out_u) {
    int warp = (blockIdx.x * blockDim.x + threadIdx.x) >> 5;
    int lane = threadIdx.x & 31;
    if (warp < N_SPOT) {
        const float* x = hs + (size_t)warp * HID;
        float s = 0.f;
#pragma unroll
        for (int i = lane; i < HID; i += 32) s += x[i] * Ws[i];
#pragma unroll
        for (int o = 16; o; o >>= 1) s += __shfl_down_sync(0xffffffffu, s, o);
        if (lane == 0) out_s[warp] = s + bs[0];
    } else if (warp < 2 * N_SPOT) {
        int n = warp - N_SPOT;
        const float* x = hu + (size_t)n * HID;
        float s = 0.f;
#pragma unroll
        for (int i = lane; i < HID; i += 32) s += x[i] * Wu[i];
#pragma unroll
        for (int o = 16; o; o >>= 1) s += __shfl_down_sync(0xffffffffu, s, o);
        if (lane == 0) out_u[n] = s + bu[0];
    }
}

// ---------------- host ----------------
static float* sym_addr(const void* sym) {
    void* p = nullptr;
    cudaGetSymbolAddress(&p, sym);
    return (float*)p;
}

extern "C" void kernel_launch(void* const* d_in, const int* in_sizes, int n_in,
                              void* d_out, int out_size) {
    const float* x_spot  = (const float*)d_in[0];
    const float* x_user  = (const float*)d_in[1];
    const int*   edge_us = (const int*)d_in[2];
    const int*   edge_su = (const int*)d_in[3];
    const float* W_att   = (const float*)d_in[4];
    const float* q_att   = (const float*)d_in[5];
    const float* W0_us   = (const float*)d_in[6];
    const float* W0_su   = (const float*)d_in[7];
    const float* Wmid_us = (const float*)d_in[8];
    const float* Wmid_su = (const float*)d_in[9];
    const float* W_out_s = (const float*)d_in[10];
    const float* b_out_s = (const float*)d_in[11];
    const float* W_out_u = (const float*)d_in[12];
    const float* b_out_u = (const float*)d_in[13];
    float* out = (float*)d_out;

    float* p_wq    = sym_addr(g_wq);
    float* p_Y     = sym_addr(g_Y);
    float* p_xs    = sym_addr(g_xs);
    float* p_tmp_u = sym_addr(g_tmp_u);
    float* p_tmp_s = sym_addr(g_tmp_s);
    float* p_hs0   = sym_addr(g_hs0);
    float* p_hs1   = sym_addr(g_hs1);
    float* p_hu0   = sym_addr(g_hu0);
    float* p_hu1   = sym_addr(g_hu1);
    float* p_acc_s = sym_addr(g_acc_s);
    float* p_acc_u = sym_addr(g_acc_u);
    float* p_inv_us = sym_addr(g_inv_us);
    float* p_inv_su = sym_addr(g_inv_su);
    float* p_deg   = sym_addr(g_deg);

    const size_t HBYTES = (size_t)N_SPOT * HID * sizeof(float);
    const int NHID = N_SPOT * HID;

    // degrees + normalization
    cudaMemsetAsync(p_deg, 0, 4 * N_SPOT * sizeof(float));
    cudaMemsetAsync(p_acc_s, 0, HBYTES);
    cudaMemsetAsync(p_acc_u, 0, HBYTES);
    int eb = (NE + 255) / 256;
    deg_count_kernel<<<eb, 256>>>(edge_us,      p_deg + 0 * N_SPOT, NE);  // user deg (us src)
    deg_count_kernel<<<eb, 256>>>(edge_us + NE, p_deg + 1 * N_SPOT, NE);  // spot deg (us dst)
    deg_count_kernel<<<eb, 256>>>(edge_su,      p_deg + 2 * N_SPOT, NE);  // spot deg (su src)
    deg_count_kernel<<<eb, 256>>>(edge_su + NE, p_deg + 3 * N_SPOT, NE);  // user deg (su dst)
    inv_div_kernel<<<eb, 256>>>(edge_us, edge_us + NE, p_deg + 0 * N_SPOT, p_deg + 1 * N_SPOT, p_inv_us, NE);
    inv_div_kernel<<<eb, 256>>>(edge_su, edge_su + NE, p_deg + 2 * N_SPOT, p_deg + 3 * N_SPOT, p_inv_su, NE);

    // attention
    wq_kernel<<<(HEADS * ATT_IN + 255) / 256, 256>>>(W_att, q_att, p_wq);
    att_kernel<<<N_SPOT, 128>>>(x_spot, p_wq, p_Y);
    dim3 gatt((N_SPOT + 63) / 64, PER / 64);
    for (int h = 0; h < HEADS; h++) {
        sgemm_kernel<<<gatt, 256>>>(p_Y + (size_t)h * N_SPOT * ATT_IN, ATT_IN,
                                    W_att + (size_t)h * ATT_IN * PER, PER,
                                    p_xs + h * PER, ATT_IN, N_SPOT, ATT_IN);
    }

    dim3 g256((N_SPOT + 63) / 64, HID / 64);
    int sb = (NE * 64 + 255) / 256;
    int rb = (NHID + 255) / 256;

    // ---- layer 0 ----
    sgemm_kernel<<<g256, 256>>>(x_user, 512, W0_us, HID, p_tmp_u, HID, N_USER, 512);
    sgemm_kernel<<<g256, 256>>>(p_xs, ATT_IN, W0_su, HID, p_tmp_s, HID, N_SPOT, ATT_IN);
    cudaMemsetAsync(p_hs0, 0, HBYTES);
    cudaMemsetAsync(p_hu0, 0, HBYTES);
    scatter_kernel<<<sb, 256>>>(p_tmp_u, edge_us, edge_us + NE, p_inv_us, p_hs0, NE);
    scatter_kernel<<<sb, 256>>>(p_tmp_s, edge_su, edge_su + NE, p_inv_su, p_hu0, NE);
    relu_acc_kernel<<<rb, 256>>>(p_hs0, p_acc_s, NHID);
    relu_acc_kernel<<<rb, 256>>>(p_hu0, p_acc_u, NHID);

    // ---- layers 1 & 2 ----
    float* hs_cur = p_hs0; float* hu_cur = p_hu0;
    float* hs_nxt = p_hs1; float* hu_nxt = p_hu1;
    for (int l = 1; l < 3; l++) {
        const float* Wu = Wmid_us + (size_t)(l - 1) * HID * HID;
        const float* Ws = Wmid_su + (size_t)(l - 1) * HID * HID;
        sgemm_kernel<<<g256, 256>>>(hu_cur, HID, Wu, HID, p_tmp_u, HID, N_USER, HID);
        sgemm_kernel<<<g256, 256>>>(hs_cur, HID, Ws, HID, p_tmp_s, HID, N_SPOT, HID);
        cudaMemsetAsync(hs_nxt, 0, HBYTES);
        cudaMemsetAsync(hu_nxt, 0, HBYTES);
        scatter_kernel<<<sb, 256>>>(p_tmp_u, edge_us, edge_us + NE, p_inv_us, hs_nxt, NE);
        scatter_kernel<<<sb, 256>>>(p_tmp_s, edge_su, edge_su + NE, p_inv_su, hu_nxt, NE);
        relu_acc_kernel<<<rb, 256>>>(hs_nxt, p_acc_s, NHID);
        relu_acc_kernel<<<rb, 256>>>(hu_nxt, p_acc_u, NHID);
        float* t;
        t = hs_cur; hs_cur = hs_nxt; hs_nxt = t;
        t = hu_cur; hu_cur = hu_nxt; hu_nxt = t;
    }

    // ---- outputs ----
    mean_kernel<<<rb, 256>>>(p_acc_s, p_acc_u, out, NHID);
    out_head_kernel<<<(2 * N_SPOT * 32 + 255) / 256, 256>>>(
        hs_cur, hu_cur, W_out_s, b_out_s, W_out_u, b_out_u,
        out + 2 * (size_t)NHID, out + 2 * (size_t)NHID + N_SPOT);
}

// round 2
// speedup vs baseline: 1.6871x; 1.6871x over previous
#include <cuda_runtime.h>
#include <cstdint>

#define N_SPOT 30000
#define N_USER 30000
#define NE     600000
#define SPLIT  5
#define ATT_IN 512
#define HEADS  4
#define PER    128
#define HID    256

// ---------------- scratch (device globals; no allocation) ----------------
__device__ float g_wq[HEADS * ATT_IN];
__device__ float g_Y[(size_t)HEADS * N_SPOT * ATT_IN];
__device__ float g_xs[(size_t)N_SPOT * ATT_IN];
__device__ float g_tmp_u[(size_t)N_USER * HID];
__device__ float g_tmp_s[(size_t)N_SPOT * HID];
__device__ float g_hs[3][(size_t)N_SPOT * HID];
__device__ float g_hu[3][(size_t)N_USER * HID];
__device__ float g_inv_us[NE];
__device__ float g_inv_su[NE];
__device__ float g_deg[4 * N_SPOT];

// ---------------- degree / normalization ----------------
__global__ void deg_count_kernel(const int* __restrict__ idx, float* __restrict__ deg, int n) {
    int i = blockIdx.x * blockDim.x + threadIdx.x;
    if (i < n) atomicAdd(&deg[idx[i]], 1.0f);
}

__global__ void inv_div_kernel(const int* __restrict__ src, const int* __restrict__ dst,
                               const float* __restrict__ deg_s, const float* __restrict__ deg_d,
                               float* __restrict__ inv, int n) {
    int e = blockIdx.x * blockDim.x + threadIdx.x;
    if (e < n) inv[e] = rsqrtf(deg_s[src[e]] * deg_d[dst[e]]);
}

// ---------------- attention ----------------
__global__ void wq_kernel(const float* __restrict__ W, const float* __restrict__ q,
                          float* __restrict__ wq) {
    int t = blockIdx.x * blockDim.x + threadIdx.x;
    if (t >= HEADS * ATT_IN) return;
    int h = t / ATT_IN, i = t % ATT_IN;
    const float* w = W + ((size_t)h * ATT_IN + i) * PER;
    const float* qq = q + h * PER;
    float s = 0.f;
#pragma unroll 8
    for (int p = 0; p < PER; p++) s += w[p] * qq[p];
    wq[t] = s;
}

__global__ __launch_bounds__(128) void att_kernel(const float* __restrict__ x,
                                                  const float* __restrict__ wq,
                                                  float* __restrict__ Y) {
    int n = blockIdx.x;
    __shared__ float sx[SPLIT * ATT_IN];
    __shared__ float satt[HEADS][SPLIT];
    const float* xr = x + (size_t)n * (SPLIT * ATT_IN);
    for (int i = threadIdx.x; i < SPLIT * ATT_IN; i += 128) sx[i] = xr[i];
    __syncthreads();

    int w = threadIdx.x >> 5, lane = threadIdx.x & 31;
    if (w < HEADS) {
        float lg[SPLIT];
#pragma unroll
        for (int s = 0; s < SPLIT; s++) {
            float p = 0.f;
            for (int i = lane; i < ATT_IN; i += 32) p += sx[s * ATT_IN + i] * wq[w * ATT_IN + i];
#pragma unroll
            for (int o = 16; o; o >>= 1) p += __shfl_down_sync(0xffffffffu, p, o);
            lg[s] = p;
        }
        if (lane == 0) {
            float mx = -1e30f;
#pragma unroll
            for (int s = 0; s < SPLIT; s++) {
                lg[s] = lg[s] >= 0.f ? lg[s] : 0.2f * lg[s];
                mx = fmaxf(mx, lg[s]);
            }
            float sum = 0.f;
#pragma unroll
            for (int s = 0; s < SPLIT; s++) { lg[s] = expf(lg[s] - mx); sum += lg[s]; }
            float r = 1.f / sum;
#pragma unroll
            for (int s = 0; s < SPLIT; s++) satt[w][s] = lg[s] * r;
        }
    }
    __syncthreads();

#pragma unroll
    for (int h = 0; h < HEADS; h++) {
        float a0 = satt[h][0], a1 = satt[h][1], a2 = satt[h][2], a3 = satt[h][3], a4 = satt[h][4];
        for (int i = threadIdx.x; i < ATT_IN; i += 128) {
            float y = a0 * sx[i] + a1 * sx[ATT_IN + i] + a2 * sx[2 * ATT_IN + i]
                    + a3 * sx[3 * ATT_IN + i] + a4 * sx[4 * ATT_IN + i];
            Y[((size_t)h * N_SPOT + n) * ATT_IN + i] = y;
        }
    }
}

// ---------------- 128x128 double-buffered fp32 GEMM ----------------
// C[M,N] = op(A)[M,K] @ B[K,N]; op = ReLU if RELUA. N mult of 128, K mult of 16.
// grid: (ceil(M/128), N/128, batch)
template <bool RELUA>
__global__ __launch_bounds__(256, 2) void sgemm128(const float* __restrict__ A, int lda,
                                                   const float* __restrict__ B, int ldb,
                                                   float* __restrict__ C, int ldc,
                                                   int M, int K,
                                                   long sA, long sB, long sC) {
    A += (long)blockIdx.z * sA;
    B += (long)blockIdx.z * sB;
    C += (long)blockIdx.z * sC;

    __shared__ __align__(16) float As[2][16][132];
    __shared__ __align__(16) float Bs[2][16][128];

    const int tid = threadIdx.x;
    const int m0 = blockIdx.x * 128, n0 = blockIdx.y * 128;

    // A-tile load mapping: 512 float4 / 256 thr = 2 per thread
    const int ar = tid >> 2;            // rows 0..63 (and +64)
    const int ac = (tid & 3) << 2;      // col within 16-wide k tile
    const int rowA0 = m0 + ar;
    const int rowA1 = m0 + ar + 64;
    const bool v0 = rowA0 < M, v1 = rowA1 < M;
    // B-tile load mapping
    const int br = tid >> 5;            // rows 0..7 (and +8)
    const int bc = (tid & 31) << 2;     // col 0..124

    const int ty8 = (tid >> 4) << 3;
    const int tx8 = (tid & 15) << 3;

    float4 a0, a1, b0, b1;
    float acc[8][8] = {};

#define LOADREG(k0)                                                                      \
    {                                                                                    \
        a0 = v0 ? *(const float4*)(A + (size_t)rowA0 * lda + (k0) + ac)                  \
                : make_float4(0.f, 0.f, 0.f, 0.f);                                       \
        a1 = v1 ? *(const float4*)(A + (size_t)rowA1 * lda + (k0) + ac)                  \
                : make_float4(0.f, 0.f, 0.f, 0.f);                                       \
        b0 = *(const float4*)(B + (size_t)((k0) + br) * ldb + n0 + bc);                  \
        b1 = *(const float4*)(B + (size_t)((k0) + br + 8) * ldb + n0 + bc);              \
        if (RELUA) {                                                                     \
            a0.x = fmaxf(a0.x, 0.f); a0.y = fmaxf(a0.y, 0.f);                            \
            a0.z = fmaxf(a0.z, 0.f); a0.w = fmaxf(a0.w, 0.f);                            \
            a1.x = fmaxf(a1.x, 0.f); a1.y = fmaxf(a1.y, 0.f);                            \
            a1.z = fmaxf(a1.z, 0.f); a1.w = fmaxf(a1.w, 0.f);                            \
        }                                                                                \
    }

#define STORE(buf)                                                                       \
    {                                                                                    \
        As[buf][ac + 0][ar] = a0.x; As[buf][ac + 1][ar] = a0.y;                          \
        As[buf][ac + 2][ar] = a0.z; As[buf][ac + 3][ar] = a0.w;                          \
        As[buf][ac + 0][ar + 64] = a1.x; As[buf][ac + 1][ar + 64] = a1.y;                \
        As[buf][ac + 2][ar + 64] = a1.z; As[buf][ac + 3][ar + 64] = a1.w;                \
        *(float4*)&Bs[buf][br][bc] = b0;                                                 \
        *(float4*)&Bs[buf][br + 8][bc] = b1;                                             \
    }

#define COMPUTE(buf)                                                                     \
    _Pragma("unroll")                                                                    \
    for (int k = 0; k < 16; k++) {                                                       \
        float4 pa0 = *(const float4*)&As[buf][k][ty8];                                   \
        float4 pa1 = *(const float4*)&As[buf][k][ty8 + 4];                               \
        float4 pb0 = *(const float4*)&Bs[buf][k][tx8];                                   \
        float4 pb1 = *(const float4*)&Bs[buf][k][tx8 + 4];                               \
        float ra[8] = {pa0.x, pa0.y, pa0.z, pa0.w, pa1.x, pa1.y, pa1.z, pa1.w};          \
        float rb[8] = {pb0.x, pb0.y, pb0.z, pb0.w, pb1.x, pb1.y, pb1.z, pb1.w};          \
        _Pragma("unroll")                                                                \
        for (int i = 0; i < 8; i++)                                                      \
            _Pragma("unroll")                                                            \
            for (int j = 0; j < 8; j++) acc[i][j] += ra[i] * rb[j];                      \
    }

    LOADREG(0);
    STORE(0);
    __syncthreads();
    int buf = 0;
    for (int k0 = 16; k0 < K; k0 += 16) {
        LOADREG(k0);
        COMPUTE(buf);
        STORE(buf ^ 1);
        __syncthreads();
        buf ^= 1;
    }
    COMPUTE(buf);

#pragma unroll
    for (int i = 0; i < 8; i++) {
        int m = m0 + ty8 + i;
        if (m < M) {
            float4 w0 = make_float4(acc[i][0], acc[i][1], acc[i][2], acc[i][3]);
            float4 w1 = make_float4(acc[i][4], acc[i][5], acc[i][6], acc[i][7]);
            *(float4*)(C + (size_t)m * ldc + n0 + tx8) = w0;
            *(float4*)(C + (size_t)m * ldc + n0 + tx8 + 4) = w1;
        }
    }
#undef LOADREG
#undef STORE
#undef COMPUTE
}

// ---------------- edge scatter: out[dst] += msg[src] * inv ----------------
__global__ void scatter_kernel(const float* __restrict__ msg, const int* __restrict__ src,
                               const int* __restrict__ dst, const float* __restrict__ invd,
                               float* __restrict__ out, int n) {
    int idx = blockIdx.x * blockDim.x + threadIdx.x;
    int e = idx >> 6;  // HID=256 floats = 64 float4 per edge
    int c = idx & 63;
    if (e >= n) return;
    int s = src[e], d = dst[e];
    float sc = invd[e];
    float4 v = ((const float4*)msg)[(size_t)s * 64 + c];
    float* o = out + (size_t)d * HID + c * 4;
    asm volatile("red.global.add.v4.f32 [%0], {%1, %2, %3, %4};"
                 :: "l"(o), "f"(v.x * sc), "f"(v.y * sc), "f"(v.z * sc), "f"(v.w * sc)
                 : "memory");
}

// ---------------- outputs ----------------
__global__ void mean_kernel(const float* __restrict__ s0, const float* __restrict__ s1,
                            const float* __restrict__ s2,
                            const float* __restrict__ u0, const float* __restrict__ u1,
                            const float* __restrict__ u2,
                            float* __restrict__ out, int n) {
    int i = blockIdx.x * blockDim.x + threadIdx.x;
    if (i < n) {
        const float r = 1.f / 3.f;
        out[i] = (fmaxf(s0[i], 0.f) + fmaxf(s1[i], 0.f) + fmaxf(s2[i], 0.f)) * r;
        out[n + i] = (fmaxf(u0[i], 0.f) + fmaxf(u1[i], 0.f) + fmaxf(u2[i], 0.f)) * r;
    }
}

__global__ void out_head_kernel(const float* __restrict__ hs, const float* __restrict__ hu,
                                const float* __restrict__ Ws, const float* __restrict__ bs,
                                const float* __restrict__ Wu, const float* __restrict__ bu,
                                float* __restrict__ out_s, float* __restrict__ out_u) {
    int warp = (blockIdx.x * blockDim.x + threadIdx.x) >> 5;
    int lane = threadIdx.x & 31;
    if (warp < N_SPOT) {
        const float* x = hs + (size_t)warp * HID;
        float s = 0.f;
#pragma unroll
        for (int i = lane; i < HID; i += 32) s += fmaxf(x[i], 0.f) * Ws[i];
#pragma unroll
        for (int o = 16; o; o >>= 1) s += __shfl_down_sync(0xffffffffu, s, o);
        if (lane == 0) out_s[warp] = s + bs[0];
    } else if (warp < 2 * N_SPOT) {
        int n = warp - N_SPOT;
        const float* x = hu + (size_t)n * HID;
        float s = 0.f;
#pragma unroll
        for (int i = lane; i < HID; i += 32) s += fmaxf(x[i], 0.f) * Wu[i];
#pragma unroll
        for (int o = 16; o; o >>= 1) s += __shfl_down_sync(0xffffffffu, s, o);
        if (lane == 0) out_u[n] = s + bu[0];
    }
}

// ---------------- host ----------------
static float* sym_addr(const void* sym) {
    void* p = nullptr;
    cudaGetSymbolAddress(&p, sym);
    return (float*)p;
}

extern "C" void kernel_launch(void* const* d_in, const int* in_sizes, int n_in,
                              void* d_out, int out_size) {
    const float* x_spot  = (const float*)d_in[0];
    const float* x_user  = (const float*)d_in[1];
    const int*   edge_us = (const int*)d_in[2];
    const int*   edge_su = (const int*)d_in[3];
    const float* W_att   = (const float*)d_in[4];
    const float* q_att   = (const float*)d_in[5];
    const float* W0_us   = (const float*)d_in[6];
    const float* W0_su   = (const float*)d_in[7];
    const float* Wmid_us = (const float*)d_in[8];
    const float* Wmid_su = (const float*)d_in[9];
    const float* W_out_s = (const float*)d_in[10];
    const float* b_out_s = (const float*)d_in[11];
    const float* W_out_u = (const float*)d_in[12];
    const float* b_out_u = (const float*)d_in[13];
    float* out = (float*)d_out;

    float* p_wq    = sym_addr(g_wq);
    float* p_Y     = sym_addr(g_Y);
    float* p_xs    = sym_addr(g_xs);
    float* p_tmp_u = sym_addr(g_tmp_u);
    float* p_tmp_s = sym_addr(g_tmp_s);
    float* p_hs    = sym_addr(g_hs);   // 3 consecutive buffers
    float* p_hu    = sym_addr(g_hu);
    float* p_inv_us = sym_addr(g_inv_us);
    float* p_inv_su = sym_addr(g_inv_su);
    float* p_deg   = sym_addr(g_deg);

    const size_t HN = (size_t)N_SPOT * HID;
    const size_t HBYTES = HN * sizeof(float);
    const int NHID = N_SPOT * HID;

    // degrees + normalization
    cudaMemsetAsync(p_deg, 0, 4 * N_SPOT * sizeof(float));
    int eb = (NE + 255) / 256;
    deg_count_kernel<<<eb, 256>>>(edge_us,      p_deg + 0 * N_SPOT, NE);
    deg_count_kernel<<<eb, 256>>>(edge_us + NE, p_deg + 1 * N_SPOT, NE);
    deg_count_kernel<<<eb, 256>>>(edge_su,      p_deg + 2 * N_SPOT, NE);
    deg_count_kernel<<<eb, 256>>>(edge_su + NE, p_deg + 3 * N_SPOT, NE);
    inv_div_kernel<<<eb, 256>>>(edge_us, edge_us + NE, p_deg + 0 * N_SPOT, p_deg + 1 * N_SPOT, p_inv_us, NE);
    inv_div_kernel<<<eb, 256>>>(edge_su, edge_su + NE, p_deg + 2 * N_SPOT, p_deg + 3 * N_SPOT, p_inv_su, NE);

    // attention
    wq_kernel<<<(HEADS * ATT_IN + 255) / 256, 256>>>(W_att, q_att, p_wq);
    att_kernel<<<N_SPOT, 128>>>(x_spot, p_wq, p_Y);
    // pooled @ W_att per head (batched over grid.z): xs[:, h*128:(h+1)*128]
    sgemm128<false><<<dim3((N_SPOT + 127) / 128, 1, HEADS), 256>>>(
        p_Y, ATT_IN, W_att, PER, p_xs, ATT_IN, N_SPOT, ATT_IN,
        (long)N_SPOT * ATT_IN, (long)ATT_IN * PER, (long)PER);

    dim3 gL((N_SPOT + 127) / 128, HID / 128, 1);
    int sb = (NE * 64 + 255) / 256;
    int rb = (NHID + 255) / 256;

    // ---- layer 0 ----
    sgemm128<false><<<gL, 256>>>(x_user, 512, W0_us, HID, p_tmp_u, HID, N_USER, 512, 0, 0, 0);
    sgemm128<false><<<gL, 256>>>(p_xs, ATT_IN, W0_su, HID, p_tmp_s, HID, N_SPOT, ATT_IN, 0, 0, 0);
    cudaMemsetAsync(p_hs, 0, HBYTES);
    cudaMemsetAsync(p_hu, 0, HBYTES);
    scatter_kernel<<<sb, 256>>>(p_tmp_u, edge_us, edge_us + NE, p_inv_us, p_hs, NE);
    scatter_kernel<<<sb, 256>>>(p_tmp_s, edge_su, edge_su + NE, p_inv_su, p_hu, NE);

    // ---- layers 1 & 2 (ReLU applied on GEMM A-load) ----
    for (int l = 1; l < 3; l++) {
        const float* Wu = Wmid_us + (size_t)(l - 1) * HID * HID;
        const float* Ws = Wmid_su + (size_t)(l - 1) * HID * HID;
        float* hs_prev = p_hs + (l - 1) * HN;
        float* hu_prev = p_hu + (l - 1) * HN;
        float* hs_new  = p_hs + l * HN;
        float* hu_new  = p_hu + l * HN;
        sgemm128<true><<<gL, 256>>>(hu_prev, HID, Wu, HID, p_tmp_u, HID, N_USER, HID, 0, 0, 0);
        sgemm128<true><<<gL, 256>>>(hs_prev, HID, Ws, HID, p_tmp_s, HID, N_SPOT, HID, 0, 0, 0);
        cudaMemsetAsync(hs_new, 0, HBYTES);
        cudaMemsetAsync(hu_new, 0, HBYTES);
        scatter_kernel<<<sb, 256>>>(p_tmp_u, edge_us, edge_us + NE, p_inv_us, hs_new, NE);
        scatter_kernel<<<sb, 256>>>(p_tmp_s, edge_su, edge_su + NE, p_inv_su, hu_new, NE);
    }

    // ---- outputs ----
    mean_kernel<<<rb, 256>>>(p_hs, p_hs + HN, p_hs + 2 * HN,
                             p_hu, p_hu + HN, p_hu + 2 * HN, out, NHID);
    out_head_kernel<<<(2 * N_SPOT * 32 + 255) / 256, 256>>>(
        p_hs + 2 * HN, p_hu + 2 * HN, W_out_s, b_out_s, W_out_u, b_out_u,
        out + 2 * (size_t)NHID, out + 2 * (size_t)NHID + N_SPOT);
}

// round 3
// speedup vs baseline: 2.1646x; 1.2830x over previous
#include <cuda_runtime.h>
#include <cstdint>

#define N_SPOT 30000
#define N_USER 30000
#define NE     600000
#define SPLIT  5
#define ATT_IN 512
#define HEADS  4
#define PER    128
#define HID    256

// ---------------- scratch (device globals; no allocation) ----------------
__device__ float g_wq[HEADS * ATT_IN];
__device__ float g_Y[(size_t)HEADS * N_SPOT * ATT_IN];
__device__ float g_xs[(size_t)N_SPOT * ATT_IN];
__device__ float g_tmp_u[(size_t)N_USER * HID];
__device__ float g_tmp_s[(size_t)N_SPOT * HID];
__device__ float g_hs[3][(size_t)N_SPOT * HID];
__device__ float g_hu[3][(size_t)N_USER * HID];
__device__ float g_deg[4 * N_SPOT];   // [us_src(user), us_dst(spot), su_src(spot), su_dst(user)]
__device__ int   g_off_us[N_SPOT + 1];
__device__ int   g_cur_us[N_SPOT];
__device__ int   g_csr_us[NE];
__device__ int   g_off_su[N_USER + 1];
__device__ int   g_cur_su[N_USER];
__device__ int   g_csr_su[NE];

// ---------------- degree ----------------
__global__ void deg_count_kernel(const int* __restrict__ idx, float* __restrict__ deg, int n) {
    int i = blockIdx.x * blockDim.x + threadIdx.x;
    if (i < n) atomicAdd(&deg[idx[i]], 1.0f);
}

// ---------------- CSR build ----------------
// single block, 1024 threads: exclusive scan of (int)deg into off[] and cur[]
__global__ __launch_bounds__(1024) void scan_kernel(const float* __restrict__ deg,
                                                    int* __restrict__ off,
                                                    int* __restrict__ cur, int n) {
    __shared__ int part[1024];
    const int t = threadIdx.x;
    const int CH = (n + 1023) / 1024;
    const int base = t * CH;
    int s = 0;
    for (int j = 0; j < CH; j++) {
        int idx = base + j;
        if (idx < n) s += (int)deg[idx];
    }
    part[t] = s;
    __syncthreads();
    for (int o = 1; o < 1024; o <<= 1) {
        int v = (t >= o) ? part[t - o] : 0;
        __syncthreads();
        part[t] += v;
        __syncthreads();
    }
    int run = t ? part[t - 1] : 0;
    for (int j = 0; j < CH; j++) {
        int idx = base + j;
        if (idx < n) {
            off[idx] = run;
            cur[idx] = run;
            run += (int)deg[idx];
        }
    }
    if (t == 0) off[n] = part[1023];
}

__global__ void fill_kernel(const int* __restrict__ src, const int* __restrict__ dst,
                            int* __restrict__ cur, int* __restrict__ csr, int n) {
    int e = blockIdx.x * blockDim.x + threadIdx.x;
    if (e < n) {
        int p = atomicAdd(&cur[dst[e]], 1);
        csr[p] = src[e];
    }
}

// ---------------- attention ----------------
__global__ void wq_kernel(const float* __restrict__ W, const float* __restrict__ q,
                          float* __restrict__ wq) {
    int t = blockIdx.x * blockDim.x + threadIdx.x;
    if (t >= HEADS * ATT_IN) return;
    int h = t / ATT_IN, i = t % ATT_IN;
    const float* w = W + ((size_t)h * ATT_IN + i) * PER;
    const float* qq = q + h * PER;
    float s = 0.f;
#pragma unroll 8
    for (int p = 0; p < PER; p++) s += w[p] * qq[p];
    wq[t] = s;
}

__global__ __launch_bounds__(128) void att_kernel(const float* __restrict__ x,
                                                  const float* __restrict__ wq,
                                                  float* __restrict__ Y) {
    int n = blockIdx.x;
    __shared__ float sx[SPLIT * ATT_IN];
    __shared__ float satt[HEADS][SPLIT];
    const float* xr = x + (size_t)n * (SPLIT * ATT_IN);
    for (int i = threadIdx.x; i < SPLIT * ATT_IN; i += 128) sx[i] = xr[i];
    __syncthreads();

    int w = threadIdx.x >> 5, lane = threadIdx.x & 31;
    if (w < HEADS) {
        float lg[SPLIT];
#pragma unroll
        for (int s = 0; s < SPLIT; s++) {
            float p = 0.f;
            for (int i = lane; i < ATT_IN; i += 32) p += sx[s * ATT_IN + i] * wq[w * ATT_IN + i];
#pragma unroll
            for (int o = 16; o; o >>= 1) p += __shfl_down_sync(0xffffffffu, p, o);
            lg[s] = p;
        }
        if (lane == 0) {
            float mx = -1e30f;
#pragma unroll
            for (int s = 0; s < SPLIT; s++) {
                lg[s] = lg[s] >= 0.f ? lg[s] : 0.2f * lg[s];
                mx = fmaxf(mx, lg[s]);
            }
            float sum = 0.f;
#pragma unroll
            for (int s = 0; s < SPLIT; s++) { lg[s] = expf(lg[s] - mx); sum += lg[s]; }
            float r = 1.f / sum;
#pragma unroll
            for (int s = 0; s < SPLIT; s++) satt[w][s] = lg[s] * r;
        }
    }
    __syncthreads();

#pragma unroll
    for (int h = 0; h < HEADS; h++) {
        float a0 = satt[h][0], a1 = satt[h][1], a2 = satt[h][2], a3 = satt[h][3], a4 = satt[h][4];
        for (int i = threadIdx.x; i < ATT_IN; i += 128) {
            float y = a0 * sx[i] + a1 * sx[ATT_IN + i] + a2 * sx[2 * ATT_IN + i]
                    + a3 * sx[3 * ATT_IN + i] + a4 * sx[4 * ATT_IN + i];
            Y[((size_t)h * N_SPOT + n) * ATT_IN + i] = y;
        }
    }
}

// ---------------- 128x128 double-buffered fp32 GEMM ----------------
// C[M,N] = op(A)[M,K] @ B[K,N]; op = ReLU if RELUA; row-scaled by rsqrt(rs[m]) if SCALE.
template <bool RELUA, bool SCALE>
__global__ __launch_bounds__(256, 2) void sgemm128(const float* __restrict__ A, int lda,
                                                   const float* __restrict__ B, int ldb,
                                                   float* __restrict__ C, int ldc,
                                                   int M, int K,
                                                   long sA, long sB, long sC,
                                                   const float* __restrict__ rs) {
    A += (long)blockIdx.z * sA;
    B += (long)blockIdx.z * sB;
    C += (long)blockIdx.z * sC;

    __shared__ __align__(16) float As[2][16][132];
    __shared__ __align__(16) float Bs[2][16][128];

    const int tid = threadIdx.x;
    const int m0 = blockIdx.x * 128, n0 = blockIdx.y * 128;

    const int ar = tid >> 2;
    const int ac = (tid & 3) << 2;
    const int rowA0 = m0 + ar;
    const int rowA1 = m0 + ar + 64;
    const bool v0 = rowA0 < M, v1 = rowA1 < M;
    const int br = tid >> 5;
    const int bc = (tid & 31) << 2;

    const int ty8 = (tid >> 4) << 3;
    const int tx8 = (tid & 15) << 3;

    float4 a0, a1, b0, b1;
    float acc[8][8] = {};

#define LOADREG(k0)                                                                      \
    {                                                                                    \
        a0 = v0 ? *(const float4*)(A + (size_t)rowA0 * lda + (k0) + ac)                  \
                : make_float4(0.f, 0.f, 0.f, 0.f);                                       \
        a1 = v1 ? *(const float4*)(A + (size_t)rowA1 * lda + (k0) + ac)                  \
                : make_float4(0.f, 0.f, 0.f, 0.f);                                       \
        b0 = *(const float4*)(B + (size_t)((k0) + br) * ldb + n0 + bc);                  \
        b1 = *(const float4*)(B + (size_t)((k0) + br + 8) * ldb + n0 + bc);              \
        if (RELUA) {                                                                     \
            a0.x = fmaxf(a0.x, 0.f); a0.y = fmaxf(a0.y, 0.f);                            \
            a0.z = fmaxf(a0.z, 0.f); a0.w = fmaxf(a0.w, 0.f);                            \
            a1.x = fmaxf(a1.x, 0.f); a1.y = fmaxf(a1.y, 0.f);                            \
            a1.z = fmaxf(a1.z, 0.f); a1.w = fmaxf(a1.w, 0.f);                            \
        }                                                                                \
    }

#define STORE(buf)                                                                       \
    {                                                                                    \
        As[buf][ac + 0][ar] = a0.x; As[buf][ac + 1][ar] = a0.y;                          \
        As[buf][ac + 2][ar] = a0.z; As[buf][ac + 3][ar] = a0.w;                          \
        As[buf][ac + 0][ar + 64] = a1.x; As[buf][ac + 1][ar + 64] = a1.y;                \
        As[buf][ac + 2][ar + 64] = a1.z; As[buf][ac + 3][ar + 64] = a1.w;                \
        *(float4*)&Bs[buf][br][bc] = b0;                                                 \
        *(float4*)&Bs[buf][br + 8][bc] = b1;                                             \
    }

#define COMPUTE(buf)                                                                     \
    _Pragma("unroll")                                                                    \
    for (int k = 0; k < 16; k++) {                                                       \
        float4 pa0 = *(const float4*)&As[buf][k][ty8];                                   \
        float4 pa1 = *(const float4*)&As[buf][k][ty8 + 4];                               \
        float4 pb0 = *(const float4*)&Bs[buf][k][tx8];                                   \
        float4 pb1 = *(const float4*)&Bs[buf][k][tx8 + 4];                               \
        float ra[8] = {pa0.x, pa0.y, pa0.z, pa0.w, pa1.x, pa1.y, pa1.z, pa1.w};          \
        float rb[8] = {pb0.x, pb0.y, pb0.z, pb0.w, pb1.x, pb1.y, pb1.z, pb1.w};          \
        _Pragma("unroll")                                                                \
        for (int i = 0; i < 8; i++)                                                      \
            _Pragma("unroll")                                                            \
            for (int j = 0; j < 8; j++) acc[i][j] += ra[i] * rb[j];                      \
    }

    LOADREG(0);
    STORE(0);
    __syncthreads();
    int buf = 0;
    for (int k0 = 16; k0 < K; k0 += 16) {
        LOADREG(k0);
        COMPUTE(buf);
        STORE(buf ^ 1);
        __syncthreads();
        buf ^= 1;
    }
    COMPUTE(buf);

#pragma unroll
    for (int i = 0; i < 8; i++) {
        int m = m0 + ty8 + i;
        if (m < M) {
            float sc = 1.f;
            if (SCALE) {
                float d = rs[m];
                sc = d > 0.f ? rsqrtf(d) : 0.f;
            }
            float4 w0 = make_float4(acc[i][0] * sc, acc[i][1] * sc, acc[i][2] * sc, acc[i][3] * sc);
            float4 w1 = make_float4(acc[i][4] * sc, acc[i][5] * sc, acc[i][6] * sc, acc[i][7] * sc);
            *(float4*)(C + (size_t)m * ldc + n0 + tx8) = w0;
            *(float4*)(C + (size_t)m * ldc + n0 + tx8 + 4) = w1;
        }
    }
#undef LOADREG
#undef STORE
#undef COMPUTE
}

// ---------------- CSR segmented gather-sum ----------------
// out[node,:] = rsqrt(deg_dst[node]) * sum_{e in seg(node)} msg[csr[e],:]
// 64 threads per node (each owns one float4 of the 256-float row), 4 nodes/block.
__global__ __launch_bounds__(256) void gather_kernel(const float4* __restrict__ msg,
                                                     const int* __restrict__ off,
                                                     const int* __restrict__ csr,
                                                     const float* __restrict__ deg_dst,
                                                     float4* __restrict__ out, int n) {
    int node = blockIdx.x * 4 + (threadIdx.x >> 6);
    int c = threadIdx.x & 63;
    if (node >= n) return;
    int b = off[node], e = off[node + 1];
    float4 acc = make_float4(0.f, 0.f, 0.f, 0.f);
    int i = b;
    for (; i + 4 <= e; i += 4) {
        int s0 = __ldg(&csr[i]), s1 = __ldg(&csr[i + 1]);
        int s2 = __ldg(&csr[i + 2]), s3 = __ldg(&csr[i + 3]);
        float4 v0 = __ldg(&msg[(size_t)s0 * 64 + c]);
        float4 v1 = __ldg(&msg[(size_t)s1 * 64 + c]);
        float4 v2 = __ldg(&msg[(size_t)s2 * 64 + c]);
        float4 v3 = __ldg(&msg[(size_t)s3 * 64 + c]);
        acc.x += v0.x + v1.x + v2.x + v3.x;
        acc.y += v0.y + v1.y + v2.y + v3.y;
        acc.z += v0.z + v1.z + v2.z + v3.z;
        acc.w += v0.w + v1.w + v2.w + v3.w;
    }
    for (; i < e; i++) {
        int s0 = __ldg(&csr[i]);
        float4 v0 = __ldg(&msg[(size_t)s0 * 64 + c]);
        acc.x += v0.x; acc.y += v0.y; acc.z += v0.z; acc.w += v0.w;
    }
    float d = deg_dst[node];
    float sc = d > 0.f ? rsqrtf(d) : 0.f;
    acc.x *= sc; acc.y *= sc; acc.z *= sc; acc.w *= sc;
    out[(size_t)node * 64 + c] = acc;
}

// ---------------- outputs ----------------
__global__ void mean_kernel(const float* __restrict__ s0, const float* __restrict__ s1,
                            const float* __restrict__ s2,
                            const float* __restrict__ u0, const float* __restrict__ u1,
                            const float* __restrict__ u2,
                            float* __restrict__ out, int n) {
    int i = blockIdx.x * blockDim.x + threadIdx.x;
    if (i < n) {
        const float r = 1.f / 3.f;
        out[i] = (fmaxf(s0[i], 0.f) + fmaxf(s1[i], 0.f) + fmaxf(s2[i], 0.f)) * r;
        out[n + i] = (fmaxf(u0[i], 0.f) + fmaxf(u1[i], 0.f) + fmaxf(u2[i], 0.f)) * r;
    }
}

__global__ void out_head_kernel(const float* __restrict__ hs, const float* __restrict__ hu,
                                const float* __restrict__ Ws, const float* __restrict__ bs,
                                const float* __restrict__ Wu, const float* __restrict__ bu,
                                float* __restrict__ out_s, float* __restrict__ out_u) {
    int warp = (blockIdx.x * blockDim.x + threadIdx.x) >> 5;
    int lane = threadIdx.x & 31;
    if (warp < N_SPOT) {
        const float* x = hs + (size_t)warp * HID;
        float s = 0.f;
#pragma unroll
        for (int i = lane; i < HID; i += 32) s += fmaxf(x[i], 0.f) * Ws[i];
#pragma unroll
        for (int o = 16; o; o >>= 1) s += __shfl_down_sync(0xffffffffu, s, o);
        if (lane == 0) out_s[warp] = s + bs[0];
    } else if (warp < 2 * N_SPOT) {
        int n = warp - N_SPOT;
        const float* x = hu + (size_t)n * HID;
        float s = 0.f;
#pragma unroll
        for (int i = lane; i < HID; i += 32) s += fmaxf(x[i], 0.f) * Wu[i];
#pragma unroll
        for (int o = 16; o; o >>= 1) s += __shfl_down_sync(0xffffffffu, s, o);
        if (lane == 0) out_u[n] = s + bu[0];
    }
}

// ---------------- host ----------------
static float* sym_addr(const void* sym) {
    void* p = nullptr;
    cudaGetSymbolAddress(&p, sym);
    return (float*)p;
}
static int* sym_addr_i(const void* sym) {
    void* p = nullptr;
    cudaGetSymbolAddress(&p, sym);
    return (int*)p;
}

extern "C" void kernel_launch(void* const* d_in, const int* in_sizes, int n_in,
                              void* d_out, int out_size) {
    const float* x_spot  = (const float*)d_in[0];
    const float* x_user  = (const float*)d_in[1];
    const int*   edge_us = (const int*)d_in[2];
    const int*   edge_su = (const int*)d_in[3];
    const float* W_att   = (const float*)d_in[4];
    const float* q_att   = (const float*)d_in[5];
    const float* W0_us   = (const float*)d_in[6];
    const float* W0_su   = (const float*)d_in[7];
    const float* Wmid_us = (const float*)d_in[8];
    const float* Wmid_su = (const float*)d_in[9];
    const float* W_out_s = (const float*)d_in[10];
    const float* b_out_s = (const float*)d_in[11];
    const float* W_out_u = (const float*)d_in[12];
    const float* b_out_u = (const float*)d_in[13];
    float* out = (float*)d_out;

    float* p_wq    = sym_addr(g_wq);
    float* p_Y     = sym_addr(g_Y);
    float* p_xs    = sym_addr(g_xs);
    float* p_tmp_u = sym_addr(g_tmp_u);
    float* p_tmp_s = sym_addr(g_tmp_s);
    float* p_hs    = sym_addr(g_hs);
    float* p_hu    = sym_addr(g_hu);
    float* p_deg   = sym_addr(g_deg);
    int* p_off_us  = sym_addr_i(g_off_us);
    int* p_cur_us  = sym_addr_i(g_cur_us);
    int* p_csr_us  = sym_addr_i(g_csr_us);
    int* p_off_su  = sym_addr_i(g_off_su);
    int* p_cur_su  = sym_addr_i(g_cur_su);
    int* p_csr_su  = sym_addr_i(g_csr_su);

    const size_t HN = (size_t)N_SPOT * HID;
    const int NHID = N_SPOT * HID;

    // degrees
    cudaMemsetAsync(p_deg, 0, 4 * N_SPOT * sizeof(float));
    int eb = (NE + 255) / 256;
    deg_count_kernel<<<eb, 256>>>(edge_us,      p_deg + 0 * N_SPOT, NE);
    deg_count_kernel<<<eb, 256>>>(edge_us + NE, p_deg + 1 * N_SPOT, NE);
    deg_count_kernel<<<eb, 256>>>(edge_su,      p_deg + 2 * N_SPOT, NE);
    deg_count_kernel<<<eb, 256>>>(edge_su + NE, p_deg + 3 * N_SPOT, NE);

    // CSR build (by destination)
    scan_kernel<<<1, 1024>>>(p_deg + 1 * N_SPOT, p_off_us, p_cur_us, N_SPOT);
    scan_kernel<<<1, 1024>>>(p_deg + 3 * N_SPOT, p_off_su, p_cur_su, N_USER);
    fill_kernel<<<eb, 256>>>(edge_us, edge_us + NE, p_cur_us, p_csr_us, NE);
    fill_kernel<<<eb, 256>>>(edge_su, edge_su + NE, p_cur_su, p_csr_su, NE);

    // attention
    wq_kernel<<<(HEADS * ATT_IN + 255) / 256, 256>>>(W_att, q_att, p_wq);
    att_kernel<<<N_SPOT, 128>>>(x_spot, p_wq, p_Y);
    sgemm128<false, false><<<dim3((N_SPOT + 127) / 128, 1, HEADS), 256>>>(
        p_Y, ATT_IN, W_att, PER, p_xs, ATT_IN, N_SPOT, ATT_IN,
        (long)N_SPOT * ATT_IN, (long)ATT_IN * PER, (long)PER, nullptr);

    dim3 gL((N_SPOT + 127) / 128, HID / 128, 1);
    int gb = (N_SPOT + 3) / 4;
    int rb = (NHID + 255) / 256;

    // ---- layer 0 (src-normalization folded into GEMM epilogue) ----
    sgemm128<false, true><<<gL, 256>>>(x_user, 512, W0_us, HID, p_tmp_u, HID, N_USER, 512,
                                       0, 0, 0, p_deg + 0 * N_SPOT);
    sgemm128<false, true><<<gL, 256>>>(p_xs, ATT_IN, W0_su, HID, p_tmp_s, HID, N_SPOT, ATT_IN,
                                       0, 0, 0, p_deg + 2 * N_SPOT);
    gather_kernel<<<gb, 256>>>((const float4*)p_tmp_u, p_off_us, p_csr_us,
                               p_deg + 1 * N_SPOT, (float4*)p_hs, N_SPOT);
    gather_kernel<<<gb, 256>>>((const float4*)p_tmp_s, p_off_su, p_csr_su,
                               p_deg + 3 * N_SPOT, (float4*)p_hu, N_USER);

    // ---- layers 1 & 2 (ReLU on GEMM A-load) ----
    for (int l = 1; l < 3; l++) {
        const float* Wu = Wmid_us + (size_t)(l - 1) * HID * HID;
        const float* Ws = Wmid_su + (size_t)(l - 1) * HID * HID;
        float* hs_prev = p_hs + (l - 1) * HN;
        float* hu_prev = p_hu + (l - 1) * HN;
        float* hs_new  = p_hs + l * HN;
        float* hu_new  = p_hu + l * HN;
        sgemm128<true, true><<<gL, 256>>>(hu_prev, HID, Wu, HID, p_tmp_u, HID, N_USER, HID,
                                          0, 0, 0, p_deg + 0 * N_SPOT);
        sgemm128<true, true><<<gL, 256>>>(hs_prev, HID, Ws, HID, p_tmp_s, HID, N_SPOT, HID,
                                          0, 0, 0, p_deg + 2 * N_SPOT);
        gather_kernel<<<gb, 256>>>((const float4*)p_tmp_u, p_off_us, p_csr_us,
                                   p_deg + 1 * N_SPOT, (float4*)hs_new, N_SPOT);
        gather_kernel<<<gb, 256>>>((const float4*)p_tmp_s, p_off_su, p_csr_su,
                                   p_deg + 3 * N_SPOT, (float4*)hu_new, N_USER);
    }

    // ---- outputs ----
    mean_kernel<<<rb, 256>>>(p_hs, p_hs + HN, p_hs + 2 * HN,
                             p_hu, p_hu + HN, p_hu + 2 * HN, out, NHID);
    out_head_kernel<<<(2 * N_SPOT * 32 + 255) / 256, 256>>>(
        p_hs + 2 * HN, p_hu + 2 * HN, W_out_s, b_out_s, W_out_u, b_out_u,
        out + 2 * (size_t)NHID, out + 2 * (size_t)NHID + N_SPOT);
}

// round 4
// speedup vs baseline: 2.1741x; 1.0044x over previous
#include <cuda_runtime.h>
#include <cstdint>

#define N_SPOT 30000
#define N_USER 30000
#define NE     600000
#define SPLIT  5
#define ATT_IN 512
#define HEADS  4
#define PER    128
#define HID    256

// ---------------- scratch (device globals; no allocation) ----------------
__device__ float g_wq[HEADS * ATT_IN];
__device__ float g_Y[(size_t)HEADS * N_SPOT * ATT_IN];
__device__ float g_xs[(size_t)N_SPOT * ATT_IN];
__device__ float g_tmp_u[(size_t)N_USER * HID];
__device__ float g_tmp_s[(size_t)N_SPOT * HID];
__device__ float g_hs[3][(size_t)N_SPOT * HID];
__device__ float g_hu[3][(size_t)N_USER * HID];
__device__ float g_deg[4 * N_SPOT];   // [us_src(user), us_dst(spot), su_src(spot), su_dst(user)]
__device__ int   g_off_us[N_SPOT + 1];
__device__ int   g_cur_us[N_SPOT];
__device__ int   g_csr_us[NE];
__device__ int   g_off_su[N_USER + 1];
__device__ int   g_cur_su[N_USER];
__device__ int   g_csr_su[NE];

// ---------------- degree (all four histograms in one pass) ----------------
__global__ void deg_count_kernel(const int* __restrict__ e_us, const int* __restrict__ e_su,
                                 float* __restrict__ deg) {
    int i = blockIdx.x * blockDim.x + threadIdx.x;
    if (i < NE) {
        atomicAdd(&deg[0 * N_SPOT + e_us[i]], 1.0f);
        atomicAdd(&deg[1 * N_SPOT + e_us[NE + i]], 1.0f);
        atomicAdd(&deg[2 * N_SPOT + e_su[i]], 1.0f);
        atomicAdd(&deg[3 * N_SPOT + e_su[NE + i]], 1.0f);
    }
}

// ---------------- CSR build ----------------
__global__ __launch_bounds__(1024) void scan_kernel(const float* __restrict__ deg,
                                                    int* __restrict__ off,
                                                    int* __restrict__ cur, int n) {
    __shared__ int part[1024];
    const int t = threadIdx.x;
    const int CH = (n + 1023) / 1024;
    const int base = t * CH;
    int s = 0;
    for (int j = 0; j < CH; j++) {
        int idx = base + j;
        if (idx < n) s += (int)deg[idx];
    }
    part[t] = s;
    __syncthreads();
    for (int o = 1; o < 1024; o <<= 1) {
        int v = (t >= o) ? part[t - o] : 0;
        __syncthreads();
        part[t] += v;
        __syncthreads();
    }
    int run = t ? part[t - 1] : 0;
    for (int j = 0; j < CH; j++) {
        int idx = base + j;
        if (idx < n) {
            off[idx] = run;
            cur[idx] = run;
            run += (int)deg[idx];
        }
    }
    if (t == 0) off[n] = part[1023];
}

__global__ void fill_kernel(const int* __restrict__ src, const int* __restrict__ dst,
                            int* __restrict__ cur, int* __restrict__ csr, int n) {
    int e = blockIdx.x * blockDim.x + threadIdx.x;
    if (e < n) {
        int p = atomicAdd(&cur[dst[e]], 1);
        csr[p] = src[e];
    }
}

// ---------------- attention ----------------
__global__ void wq_kernel(const float* __restrict__ W, const float* __restrict__ q,
                          float* __restrict__ wq) {
    int t = blockIdx.x * blockDim.x + threadIdx.x;
    if (t >= HEADS * ATT_IN) return;
    int h = t / ATT_IN, i = t % ATT_IN;
    const float* w = W + ((size_t)h * ATT_IN + i) * PER;
    const float* qq = q + h * PER;
    float s = 0.f;
#pragma unroll 8
    for (int p = 0; p < PER; p++) s += w[p] * qq[p];
    wq[t] = s;
}

__global__ __launch_bounds__(128) void att_kernel(const float* __restrict__ x,
                                                  const float* __restrict__ wq,
                                                  float* __restrict__ Y) {
    int n = blockIdx.x;
    __shared__ float sx[SPLIT * ATT_IN];
    __shared__ float satt[HEADS][SPLIT];
    const float* xr = x + (size_t)n * (SPLIT * ATT_IN);
    for (int i = threadIdx.x; i < SPLIT * ATT_IN; i += 128) sx[i] = xr[i];
    __syncthreads();

    int w = threadIdx.x >> 5, lane = threadIdx.x & 31;
    if (w < HEADS) {
        float lg[SPLIT];
#pragma unroll
        for (int s = 0; s < SPLIT; s++) {
            float p = 0.f;
            for (int i = lane; i < ATT_IN; i += 32) p += sx[s * ATT_IN + i] * wq[w * ATT_IN + i];
#pragma unroll
            for (int o = 16; o; o >>= 1) p += __shfl_down_sync(0xffffffffu, p, o);
            lg[s] = p;
        }
        if (lane == 0) {
            float mx = -1e30f;
#pragma unroll
            for (int s = 0; s < SPLIT; s++) {
                lg[s] = lg[s] >= 0.f ? lg[s] : 0.2f * lg[s];
                mx = fmaxf(mx, lg[s]);
            }
            float sum = 0.f;
#pragma unroll
            for (int s = 0; s < SPLIT; s++) { lg[s] = expf(lg[s] - mx); sum += lg[s]; }
            float r = 1.f / sum;
#pragma unroll
            for (int s = 0; s < SPLIT; s++) satt[w][s] = lg[s] * r;
        }
    }
    __syncthreads();

#pragma unroll
    for (int h = 0; h < HEADS; h++) {
        float a0 = satt[h][0], a1 = satt[h][1], a2 = satt[h][2], a3 = satt[h][3], a4 = satt[h][4];
        for (int i = threadIdx.x; i < ATT_IN; i += 128) {
            float y = a0 * sx[i] + a1 * sx[ATT_IN + i] + a2 * sx[2 * ATT_IN + i]
                    + a3 * sx[3 * ATT_IN + i] + a4 * sx[4 * ATT_IN + i];
            Y[((size_t)h * N_SPOT + n) * ATT_IN + i] = y;
        }
    }
}

// ---------------- 128x128 double-buffered fp32 GEMM (FFMA2 inner loop) ----------------
// C[M,N] = op(A)[M,K] @ B[K,N]; op = ReLU if RELUA; row-scaled by rsqrt(rs[m]) if SCALE.
template <bool RELUA, bool SCALE>
__global__ __launch_bounds__(256, 2) void sgemm128(const float* __restrict__ A, int lda,
                                                   const float* __restrict__ B, int ldb,
                                                   float* __restrict__ C, int ldc,
                                                   int M, int K,
                                                   long sA, long sB, long sC,
                                                   const float* __restrict__ rs) {
    A += (long)blockIdx.z * sA;
    B += (long)blockIdx.z * sB;
    C += (long)blockIdx.z * sC;

    __shared__ __align__(16) float As[2][16][132];
    __shared__ __align__(16) float Bs[2][16][128];

    const int tid = threadIdx.x;
    const int m0 = blockIdx.x * 128, n0 = blockIdx.y * 128;

    const int ar = tid >> 2;
    const int ac = (tid & 3) << 2;
    const int rowA0 = m0 + ar;
    const int rowA1 = m0 + ar + 64;
    const bool v0 = rowA0 < M, v1 = rowA1 < M;
    const int br = tid >> 5;
    const int bc = (tid & 31) << 2;

    const int ty8 = (tid >> 4) << 3;
    const int tx8 = (tid & 15) << 3;

    float4 a0, a1, b0, b1;
    // packed f32x2 accumulators: acc2[i][j] holds C columns {2j, 2j+1} for row i
    unsigned long long acc2[8][4];
#pragma unroll
    for (int i = 0; i < 8; i++)
#pragma unroll
        for (int j = 0; j < 4; j++) acc2[i][j] = 0ull;

#define LOADREG(k0)                                                                      \
    {                                                                                    \
        a0 = v0 ? *(const float4*)(A + (size_t)rowA0 * lda + (k0) + ac)                  \
                : make_float4(0.f, 0.f, 0.f, 0.f);                                       \
        a1 = v1 ? *(const float4*)(A + (size_t)rowA1 * lda + (k0) + ac)                  \
                : make_float4(0.f, 0.f, 0.f, 0.f);                                       \
        b0 = *(const float4*)(B + (size_t)((k0) + br) * ldb + n0 + bc);                  \
        b1 = *(const float4*)(B + (size_t)((k0) + br + 8) * ldb + n0 + bc);              \
        if (RELUA) {                                                                     \
            a0.x = fmaxf(a0.x, 0.f); a0.y = fmaxf(a0.y, 0.f);                            \
            a0.z = fmaxf(a0.z, 0.f); a0.w = fmaxf(a0.w, 0.f);                            \
            a1.x = fmaxf(a1.x, 0.f); a1.y = fmaxf(a1.y, 0.f);                            \
            a1.z = fmaxf(a1.z, 0.f); a1.w = fmaxf(a1.w, 0.f);                            \
        }                                                                                \
    }

#define STORE(buf)                                                                       \
    {                                                                                    \
        As[buf][ac + 0][ar] = a0.x; As[buf][ac + 1][ar] = a0.y;                          \
        As[buf][ac + 2][ar] = a0.z; As[buf][ac + 3][ar] = a0.w;                          \
        As[buf][ac + 0][ar + 64] = a1.x; As[buf][ac + 1][ar + 64] = a1.y;                \
        As[buf][ac + 2][ar + 64] = a1.z; As[buf][ac + 3][ar + 64] = a1.w;                \
        *(float4*)&Bs[buf][br][bc] = b0;                                                 \
        *(float4*)&Bs[buf][br + 8][bc] = b1;                                             \
    }

#define COMPUTE(buf)                                                                     \
    _Pragma("unroll")                                                                    \
    for (int k = 0; k < 16; k++) {                                                       \
        float4 pa0 = *(const float4*)&As[buf][k][ty8];                                   \
        float4 pa1 = *(const float4*)&As[buf][k][ty8 + 4];                               \
        ulonglong2 qb0 = *(const ulonglong2*)&Bs[buf][k][tx8];                           \
        ulonglong2 qb1 = *(const ulonglong2*)&Bs[buf][k][tx8 + 4];                       \
        float ra[8] = {pa0.x, pa0.y, pa0.z, pa0.w, pa1.x, pa1.y, pa1.z, pa1.w};          \
        _Pragma("unroll")                                                                \
        for (int i = 0; i < 8; i++) {                                                    \
            unsigned long long ad;                                                       \
            asm("mov.b64 %0, {%1, %1};" : "=l"(ad) : "f"(ra[i]));                        \
            asm("fma.rn.f32x2 %0, %1, %2, %0;" : "+l"(acc2[i][0]) : "l"(ad), "l"(qb0.x));\
            asm("fma.rn.f32x2 %0, %1, %2, %0;" : "+l"(acc2[i][1]) : "l"(ad), "l"(qb0.y));\
            asm("fma.rn.f32x2 %0, %1, %2, %0;" : "+l"(acc2[i][2]) : "l"(ad), "l"(qb1.x));\
            asm("fma.rn.f32x2 %0, %1, %2, %0;" : "+l"(acc2[i][3]) : "l"(ad), "l"(qb1.y));\
        }                                                                                \
    }

    LOADREG(0);
    STORE(0);
    __syncthreads();
    int buf = 0;
    for (int k0 = 16; k0 < K; k0 += 16) {
        LOADREG(k0);
        COMPUTE(buf);
        STORE(buf ^ 1);
        __syncthreads();
        buf ^= 1;
    }
    COMPUTE(buf);

#pragma unroll
    for (int i = 0; i < 8; i++) {
        int m = m0 + ty8 + i;
        if (m < M) {
            float sc = 1.f;
            if (SCALE) {
                float d = rs[m];
                sc = d > 0.f ? rsqrtf(d) : 0.f;
            }
            float c[8];
#pragma unroll
            for (int j = 0; j < 4; j++) {
                float lo, hi;
                asm("mov.b64 {%0, %1}, %2;" : "=f"(lo), "=f"(hi) : "l"(acc2[i][j]));
                c[2 * j] = lo * sc;
                c[2 * j + 1] = hi * sc;
            }
            float4 w0 = make_float4(c[0], c[1], c[2], c[3]);
            float4 w1 = make_float4(c[4], c[5], c[6], c[7]);
            *(float4*)(C + (size_t)m * ldc + n0 + tx8) = w0;
            *(float4*)(C + (size_t)m * ldc + n0 + tx8 + 4) = w1;
        }
    }
#undef LOADREG
#undef STORE
#undef COMPUTE
}

// ---------------- CSR segmented gather-sum ----------------
__global__ __launch_bounds__(256) void gather_kernel(const float4* __restrict__ msg,
                                                     const int* __restrict__ off,
                                                     const int* __restrict__ csr,
                                                     const float* __restrict__ deg_dst,
                                                     float4* __restrict__ out, int n) {
    int node = blockIdx.x * 4 + (threadIdx.x >> 6);
    int c = threadIdx.x & 63;
    if (node >= n) return;
    int b = off[node], e = off[node + 1];
    float4 acc = make_float4(0.f, 0.f, 0.f, 0.f);
    int i = b;
    for (; i + 4 <= e; i += 4) {
        int s0 = __ldg(&csr[i]), s1 = __ldg(&csr[i + 1]);
        int s2 = __ldg(&csr[i + 2]), s3 = __ldg(&csr[i + 3]);
        float4 v0 = __ldg(&msg[(size_t)s0 * 64 + c]);
        float4 v1 = __ldg(&msg[(size_t)s1 * 64 + c]);
        float4 v2 = __ldg(&msg[(size_t)s2 * 64 + c]);
        float4 v3 = __ldg(&msg[(size_t)s3 * 64 + c]);
        acc.x += v0.x + v1.x + v2.x + v3.x;
        acc.y += v0.y + v1.y + v2.y + v3.y;
        acc.z += v0.z + v1.z + v2.z + v3.z;
        acc.w += v0.w + v1.w + v2.w + v3.w;
    }
    for (; i < e; i++) {
        int s0 = __ldg(&csr[i]);
        float4 v0 = __ldg(&msg[(size_t)s0 * 64 + c]);
        acc.x += v0.x; acc.y += v0.y; acc.z += v0.z; acc.w += v0.w;
    }
    float d = deg_dst[node];
    float sc = d > 0.f ? rsqrtf(d) : 0.f;
    acc.x *= sc; acc.y *= sc; acc.z *= sc; acc.w *= sc;
    out[(size_t)node * 64 + c] = acc;
}

// ---------------- outputs ----------------
__global__ void mean_kernel(const float* __restrict__ s0, const float* __restrict__ s1,
                            const float* __restrict__ s2,
                            const float* __restrict__ u0, const float* __restrict__ u1,
                            const float* __restrict__ u2,
                            float* __restrict__ out, int n) {
    int i = blockIdx.x * blockDim.x + threadIdx.x;
    if (i < n) {
        const float r = 1.f / 3.f;
        out[i] = (fmaxf(s0[i], 0.f) + fmaxf(s1[i], 0.f) + fmaxf(s2[i], 0.f)) * r;
        out[n + i] = (fmaxf(u0[i], 0.f) + fmaxf(u1[i], 0.f) + fmaxf(u2[i], 0.f)) * r;
    }
}

__global__ void out_head_kernel(const float* __restrict__ hs, const float* __restrict__ hu,
                                const float* __restrict__ Ws, const float* __restrict__ bs,
                                const float* __restrict__ Wu, const float* __restrict__ bu,
                                float* __restrict__ out_s, float* __restrict__ out_u) {
    int warp = (blockIdx.x * blockDim.x + threadIdx.x) >> 5;
    int lane = threadIdx.x & 31;
    if (warp < N_SPOT) {
        const float* x = hs + (size_t)warp * HID;
        float s = 0.f;
#pragma unroll
        for (int i = lane; i < HID; i += 32) s += fmaxf(x[i], 0.f) * Ws[i];
#pragma unroll
        for (int o = 16; o; o >>= 1) s += __shfl_down_sync(0xffffffffu, s, o);
        if (lane == 0) out_s[warp] = s + bs[0];
    } else if (warp < 2 * N_SPOT) {
        int n = warp - N_SPOT;
        const float* x = hu + (size_t)n * HID;
        float s = 0.f;
#pragma unroll
        for (int i = lane; i < HID; i += 32) s += fmaxf(x[i], 0.f) * Wu[i];
#pragma unroll
        for (int o = 16; o; o >>= 1) s += __shfl_down_sync(0xffffffffu, s, o);
        if (lane == 0) out_u[n] = s + bu[0];
    }
}

// ---------------- host ----------------
static float* sym_addr(const void* sym) {
    void* p = nullptr;
    cudaGetSymbolAddress(&p, sym);
    return (float*)p;
}
static int* sym_addr_i(const void* sym) {
    void* p = nullptr;
    cudaGetSymbolAddress(&p, sym);
    return (int*)p;
}

extern "C" void kernel_launch(void* const* d_in, const int* in_sizes, int n_in,
                              void* d_out, int out_size) {
    const float* x_spot  = (const float*)d_in[0];
    const float* x_user  = (const float*)d_in[1];
    const int*   edge_us = (const int*)d_in[2];
    const int*   edge_su = (const int*)d_in[3];
    const float* W_att   = (const float*)d_in[4];
    const float* q_att   = (const float*)d_in[5];
    const float* W0_us   = (const float*)d_in[6];
    const float* W0_su   = (const float*)d_in[7];
    const float* Wmid_us = (const float*)d_in[8];
    const float* Wmid_su = (const float*)d_in[9];
    const float* W_out_s = (const float*)d_in[10];
    const float* b_out_s = (const float*)d_in[11];
    const float* W_out_u = (const float*)d_in[12];
    const float* b_out_u = (const float*)d_in[13];
    float* out = (float*)d_out;

    float* p_wq    = sym_addr(g_wq);
    float* p_Y     = sym_addr(g_Y);
    float* p_xs    = sym_addr(g_xs);
    float* p_tmp_u = sym_addr(g_tmp_u);
    float* p_tmp_s = sym_addr(g_tmp_s);
    float* p_hs    = sym_addr(g_hs);
    float* p_hu    = sym_addr(g_hu);
    float* p_deg   = sym_addr(g_deg);
    int* p_off_us  = sym_addr_i(g_off_us);
    int* p_cur_us  = sym_addr_i(g_cur_us);
    int* p_csr_us  = sym_addr_i(g_csr_us);
    int* p_off_su  = sym_addr_i(g_off_su);
    int* p_cur_su  = sym_addr_i(g_cur_su);
    int* p_csr_su  = sym_addr_i(g_csr_su);

    const size_t HN = (size_t)N_SPOT * HID;
    const int NHID = N_SPOT * HID;

    // degrees
    cudaMemsetAsync(p_deg, 0, 4 * N_SPOT * sizeof(float));
    int eb = (NE + 255) / 256;
    deg_count_kernel<<<eb, 256>>>(edge_us, edge_su, p_deg);

    // CSR build (by destination)
    scan_kernel<<<1, 1024>>>(p_deg + 1 * N_SPOT, p_off_us, p_cur_us, N_SPOT);
    scan_kernel<<<1, 1024>>>(p_deg + 3 * N_SPOT, p_off_su, p_cur_su, N_USER);
    fill_kernel<<<eb, 256>>>(edge_us, edge_us + NE, p_cur_us, p_csr_us, NE);
    fill_kernel<<<eb, 256>>>(edge_su, edge_su + NE, p_cur_su, p_csr_su, NE);

    // attention
    wq_kernel<<<(HEADS * ATT_IN + 255) / 256, 256>>>(W_att, q_att, p_wq);
    att_kernel<<<N_SPOT, 128>>>(x_spot, p_wq, p_Y);
    sgemm128<false, false><<<dim3((N_SPOT + 127) / 128, 1, HEADS), 256>>>(
        p_Y, ATT_IN, W_att, PER, p_xs, ATT_IN, N_SPOT, ATT_IN,
        (long)N_SPOT * ATT_IN, (long)ATT_IN * PER, (long)PER, nullptr);

    dim3 gL((N_SPOT + 127) / 128, HID / 128, 1);
    int gb = (N_SPOT + 3) / 4;
    int rb = (NHID + 255) / 256;

    // ---- layer 0 (src-normalization folded into GEMM epilogue) ----
    sgemm128<false, true><<<gL, 256>>>(x_user, 512, W0_us, HID, p_tmp_u, HID, N_USER, 512,
                                       0, 0, 0, p_deg + 0 * N_SPOT);
    sgemm128<false, true><<<gL, 256>>>(p_xs, ATT_IN, W0_su, HID, p_tmp_s, HID, N_SPOT, ATT_IN,
                                       0, 0, 0, p_deg + 2 * N_SPOT);
    gather_kernel<<<gb, 256>>>((const float4*)p_tmp_u, p_off_us, p_csr_us,
                               p_deg + 1 * N_SPOT, (float4*)p_hs, N_SPOT);
    gather_kernel<<<gb, 256>>>((const float4*)p_tmp_s, p_off_su, p_csr_su,
                               p_deg + 3 * N_SPOT, (float4*)p_hu, N_USER);

    // ---- layers 1 & 2 (ReLU on GEMM A-load) ----
    for (int l = 1; l < 3; l++) {
        const float* Wu = Wmid_us + (size_t)(l - 1) * HID * HID;
        const float* Ws = Wmid_su + (size_t)(l - 1) * HID * HID;
        float* hs_prev = p_hs + (l - 1) * HN;
        float* hu_prev = p_hu + (l - 1) * HN;
        float* hs_new  = p_hs + l * HN;
        float* hu_new  = p_hu + l * HN;
        sgemm128<true, true><<<gL, 256>>>(hu_prev, HID, Wu, HID, p_tmp_u, HID, N_USER, HID,
                                          0, 0, 0, p_deg + 0 * N_SPOT);
        sgemm128<true, true><<<gL, 256>>>(hs_prev, HID, Ws, HID, p_tmp_s, HID, N_SPOT, HID,
                                          0, 0, 0, p_deg + 2 * N_SPOT);
        gather_kernel<<<gb, 256>>>((const float4*)p_tmp_u, p_off_us, p_csr_us,
                                   p_deg + 1 * N_SPOT, (float4*)hs_new, N_SPOT);
        gather_kernel<<<gb, 256>>>((const float4*)p_tmp_s, p_off_su, p_csr_su,
                                   p_deg + 3 * N_SPOT, (float4*)hu_new, N_USER);
    }

    // ---- outputs ----
    mean_kernel<<<rb, 256>>>(p_hs, p_hs + HN, p_hs + 2 * HN,
                             p_hu, p_hu + HN, p_hu + 2 * HN, out, NHID);
    out_head_kernel<<<(2 * N_SPOT * 32 + 255) / 256, 256>>>(
        p_hs + 2 * HN, p_hu + 2 * HN, W_out_s, b_out_s, W_out_u, b_out_u,
        out + 2 * (size_t)NHID, out + 2 * (size_t)NHID + N_SPOT);
}

// round 7
// speedup vs baseline: 3.2649x; 1.5017x over previous
#include <cuda_runtime.h>
#include <cuda_bf16.h>
#include <cstdint>

#define N_SPOT 30000
#define N_USER 30000
#define NE     600000
#define SPLIT  5
#define ATT_IN 512
#define HEADS  4
#define PER    128
#define HID    256
#define MPAD   30080   // 235 * 128

// ---------------- scratch (device globals; no allocation) ----------------
__device__ float g_wq[HEADS * ATT_IN];
__device__ float g_xs[(size_t)N_SPOT * ATT_IN];
__device__ float g_tmp_u[(size_t)N_USER * HID];
__device__ float g_tmp_s[(size_t)N_SPOT * HID];
__device__ float g_hs[3][(size_t)N_SPOT * HID];
__device__ float g_hu[3][(size_t)N_USER * HID];
__device__ float g_deg[4 * N_SPOT];
__device__ int   g_off_us[N_SPOT + 1];
__device__ int   g_cur_us[N_SPOT];
__device__ int   g_csr_us[NE];
__device__ int   g_off_su[N_USER + 1];
__device__ int   g_cur_su[N_USER];
__device__ int   g_csr_su[NE];

// bf16 3-block split operands along K: A2 = [Ah | Al | Ah]  (K2 = 3K)
__device__ __nv_bfloat16 g_A2att[(size_t)HEADS * MPAD * 1536];  // att: K=512 -> K2=1536
__device__ __nv_bfloat16 g_Au2[(size_t)MPAD * 1536];
__device__ __nv_bfloat16 g_As2[(size_t)MPAD * 1536];
// weights transposed [N][3K] as [Bh | Bh | Bl]
#define WOFF_ATT   0
#define WOFF_L0US  (4 * 128 * 1536)
#define WOFF_L0SU  (WOFF_L0US + 256 * 1536)
#define WOFF_MUS   (WOFF_L0SU + 256 * 1536)
#define WOFF_MSU   (WOFF_MUS + 2 * 256 * 768)
#define WTOT       (WOFF_MSU + 2 * 256 * 768)
__device__ __nv_bfloat16 g_B2[WTOT];

// ---------------- helpers ----------------
__device__ __forceinline__ uint32_t smem_u32(const void* p) {
    uint32_t r;
    asm("{ .reg .u64 t; cvta.to.shared.u64 t, %1; cvt.u32.u64 %0, t; }" : "=r"(r) : "l"(p));
    return r;
}
__device__ __forceinline__ void ldsm4(uint32_t addr, uint32_t& r0, uint32_t& r1,
                                      uint32_t& r2, uint32_t& r3) {
    asm volatile("ldmatrix.sync.aligned.m8n8.x4.shared.b16 {%0,%1,%2,%3}, [%4];"
                 : "=r"(r0), "=r"(r1), "=r"(r2), "=r"(r3) : "r"(addr));
}
__device__ __forceinline__ void mma16816(float* d, const uint32_t* a, const uint32_t* b) {
    asm volatile(
        "mma.sync.aligned.m16n8k16.row.col.f32.bf16.bf16.f32 "
        "{%0,%1,%2,%3}, {%4,%5,%6,%7}, {%8,%9}, {%0,%1,%2,%3};"
        : "+f"(d[0]), "+f"(d[1]), "+f"(d[2]), "+f"(d[3])
        : "r"(a[0]), "r"(a[1]), "r"(a[2]), "r"(a[3]), "r"(b[0]), "r"(b[1]));
}
#define CP16(dst, src) \
    asm volatile("cp.async.ca.shared.global [%0], [%1], 16;" :: "r"(dst), "l"(src))
#define CPCOMMIT() asm volatile("cp.async.commit_group;" ::: "memory")

// ---------------- degree ----------------
__global__ void deg_count_kernel(const int* __restrict__ e_us, const int* __restrict__ e_su,
                                 float* __restrict__ deg) {
    int i = blockIdx.x * blockDim.x + threadIdx.x;
    if (i < NE) {
        atomicAdd(&deg[0 * N_SPOT + e_us[i]], 1.0f);
        atomicAdd(&deg[1 * N_SPOT + e_us[NE + i]], 1.0f);
        atomicAdd(&deg[2 * N_SPOT + e_su[i]], 1.0f);
        atomicAdd(&deg[3 * N_SPOT + e_su[NE + i]], 1.0f);
    }
}

// ---------------- CSR build ----------------
__global__ __launch_bounds__(1024) void scan_kernel(const float* __restrict__ deg,
                                                    int* __restrict__ off,
                                                    int* __restrict__ cur, int n) {
    __shared__ int part[1024];
    const int t = threadIdx.x;
    const int CH = (n + 1023) / 1024;
    const int base = t * CH;
    int s = 0;
    for (int j = 0; j < CH; j++) {
        int idx = base + j;
        if (idx < n) s += (int)deg[idx];
    }
    part[t] = s;
    __syncthreads();
    for (int o = 1; o < 1024; o <<= 1) {
        int v = (t >= o) ? part[t - o] : 0;
        __syncthreads();
        part[t] += v;
        __syncthreads();
    }
    int run = t ? part[t - 1] : 0;
    for (int j = 0; j < CH; j++) {
        int idx = base + j;
        if (idx < n) {
            off[idx] = run;
            cur[idx] = run;
            run += (int)deg[idx];
        }
    }
    if (t == 0) off[n] = part[1023];
}

__global__ void fill_kernel(const int* __restrict__ src, const int* __restrict__ dst,
                            int* __restrict__ cur, int* __restrict__ csr, int n) {
    int e = blockIdx.x * blockDim.x + threadIdx.x;
    if (e < n) {
        int p = atomicAdd(&cur[dst[e]], 1);
        csr[p] = src[e];
    }
}

// ---------------- weight transpose + split: W[K,N] -> B2[N][3K] = [Bh|Bh|Bl] ----------------
__global__ void wprep_kernel(const float* __restrict__ W, int K, int N,
                             __nv_bfloat16* __restrict__ B2) {
    int idx = blockIdx.x * 256 + threadIdx.x;
    if (idx >= N * K) return;
    int n = idx / K, k = idx % K;
    float v = W[(size_t)k * N + n];
    __nv_bfloat16 h = __float2bfloat16(v);
    float r = v - __bfloat162float(h);
    size_t base = (size_t)n * 3 * K;
    B2[base + k] = h;
    B2[base + K + k] = h;
    B2[base + 2 * K + k] = __float2bfloat16(r);
}

// ---------------- fp32 -> A2[M][3K] = [Ah|Al|Ah] with relu + row scale ----------------
__global__ void aconv_kernel(const float4* __restrict__ in, const float* __restrict__ deg,
                             int relu, int M, int Kq, int Mpad,
                             __nv_bfloat162* __restrict__ out2) {
    int idx = blockIdx.x * 256 + threadIdx.x;
    if (idx >= Mpad * Kq) return;
    int row = idx / Kq, q = idx - row * Kq;
    const int K = Kq * 4;
    float4 v = make_float4(0.f, 0.f, 0.f, 0.f);
    if (row < M) {
        v = in[idx];
        float d = deg[row];
        float sc = d > 0.f ? rsqrtf(d) : 0.f;
        if (relu) {
            v.x = fmaxf(v.x, 0.f); v.y = fmaxf(v.y, 0.f);
            v.z = fmaxf(v.z, 0.f); v.w = fmaxf(v.w, 0.f);
        }
        v.x *= sc; v.y *= sc; v.z *= sc; v.w *= sc;
    }
    __nv_bfloat16 hx = __float2bfloat16(v.x), hy = __float2bfloat16(v.y);
    __nv_bfloat16 hz = __float2bfloat16(v.z), hw = __float2bfloat16(v.w);
    float rx = v.x - __bfloat162float(hx), ry = v.y - __bfloat162float(hy);
    float rz = v.z - __bfloat162float(hz), rw = v.w - __bfloat162float(hw);
    __nv_bfloat162 hi0(hx, hy), hi1(hz, hw);
    __nv_bfloat162 lo0(__float2bfloat16(rx), __float2bfloat16(ry));
    __nv_bfloat162 lo1(__float2bfloat16(rz), __float2bfloat16(rw));
    size_t b2 = (size_t)row * (3 * K / 2);  // bf162 units per row
    out2[b2 + 2 * q + 0] = hi0;             // block 0: Ah
    out2[b2 + 2 * q + 1] = hi1;
    out2[b2 + K / 2 + 2 * q + 0] = lo0;     // block 1: Al
    out2[b2 + K / 2 + 2 * q + 1] = lo1;
    out2[b2 + K + 2 * q + 0] = hi0;         // block 2: Ah (dup)
    out2[b2 + K + 2 * q + 1] = hi1;
}

// ---------------- attention ----------------
__global__ void wq_kernel(const float* __restrict__ W, const float* __restrict__ q,
                          float* __restrict__ wq) {
    int t = blockIdx.x * blockDim.x + threadIdx.x;
    if (t >= HEADS * ATT_IN) return;
    int h = t / ATT_IN, i = t % ATT_IN;
    const float* w = W + ((size_t)h * ATT_IN + i) * PER;
    const float* qq = q + h * PER;
    float s = 0.f;
#pragma unroll 8
    for (int p = 0; p < PER; p++) s += w[p] * qq[p];
    wq[t] = s;
}

// per node: softmax pooling; emits [hi(512) | lo(512) | hi(512)] per head row.
__global__ __launch_bounds__(128) void att_kernel(const float* __restrict__ x,
                                                  const float* __restrict__ wq,
                                                  __nv_bfloat16* __restrict__ A2) {
    int n = blockIdx.x;
    if (n >= N_SPOT) {
        __nv_bfloat16 z = __float2bfloat16(0.f);
        for (int h = 0; h < HEADS; h++)
            for (int i = threadIdx.x; i < 1536; i += 128)
                A2[((size_t)h * MPAD + n) * 1536 + i] = z;
        return;
    }
    __shared__ float sx[SPLIT * ATT_IN];
    __shared__ float satt[HEADS][SPLIT];
    const float* xr = x + (size_t)n * (SPLIT * ATT_IN);
    for (int i = threadIdx.x; i < SPLIT * ATT_IN; i += 128) sx[i] = xr[i];
    __syncthreads();

    int w = threadIdx.x >> 5, lane = threadIdx.x & 31;
    if (w < HEADS) {
        float lg[SPLIT];
#pragma unroll
        for (int s = 0; s < SPLIT; s++) {
            float p = 0.f;
            for (int i = lane; i < ATT_IN; i += 32) p += sx[s * ATT_IN + i] * wq[w * ATT_IN + i];
#pragma unroll
            for (int o = 16; o; o >>= 1) p += __shfl_down_sync(0xffffffffu, p, o);
            lg[s] = p;
        }
        if (lane == 0) {
            float mx = -1e30f;
#pragma unroll
            for (int s = 0; s < SPLIT; s++) {
                lg[s] = lg[s] >= 0.f ? lg[s] : 0.2f * lg[s];
                mx = fmaxf(mx, lg[s]);
            }
            float sum = 0.f;
#pragma unroll
            for (int s = 0; s < SPLIT; s++) { lg[s] = expf(lg[s] - mx); sum += lg[s]; }
            float r = 1.f / sum;
#pragma unroll
            for (int s = 0; s < SPLIT; s++) satt[w][s] = lg[s] * r;
        }
    }
    __syncthreads();

#pragma unroll
    for (int h = 0; h < HEADS; h++) {
        float a0 = satt[h][0], a1 = satt[h][1], a2 = satt[h][2], a3 = satt[h][3], a4 = satt[h][4];
        for (int i = threadIdx.x; i < ATT_IN; i += 128) {
            float y = a0 * sx[i] + a1 * sx[ATT_IN + i] + a2 * sx[2 * ATT_IN + i]
                    + a3 * sx[3 * ATT_IN + i] + a4 * sx[4 * ATT_IN + i];
            __nv_bfloat16 hh = __float2bfloat16(y);
            float r = y - __bfloat162float(hh);
            size_t base = ((size_t)h * MPAD + n) * 1536;
            A2[base + i] = hh;
            A2[base + 512 + i] = __float2bfloat16(r);
            A2[base + 1024 + i] = hh;
        }
    }
}

// ---------------- bf16 HMMA GEMM: C[M, gridDim.y*128] = A2[M,K2] @ B2[N,K2]^T ----------------
// 256 threads, 8 warps (4M x 2N), warp tile 32x64, mma.m16n8k16, cp.async double buffer KB=64.
__global__ __launch_bounds__(256, 2) void hmma_gemm(
    const __nv_bfloat16* __restrict__ A2, const __nv_bfloat16* __restrict__ B2,
    float* __restrict__ C, int ldc, int M, int K2,
    long sA, long sB, long sC) {
    extern __shared__ __align__(16) char smem[];
    uint32_t sb = smem_u32(smem);
    const int tid = threadIdx.x;
    const int wid = tid >> 5, lane = tid & 31;
    A2 += (long)blockIdx.z * sA;
    B2 += (long)blockIdx.z * sB;
    C  += (long)blockIdx.z * sC;
    const int m0 = blockIdx.x * 128;
    const int n0 = blockIdx.y * 128;
    const int wm = (wid & 3) * 32;
    const int wn = (wid >> 2) * 64;

    float acc[2][8][4];
#pragma unroll
    for (int i = 0; i < 2; i++)
#pragma unroll
        for (int j = 0; j < 8; j++)
#pragma unroll
            for (int v = 0; v < 4; v++) acc[i][j][v] = 0.f;

#define COPY(buf, k0)                                                                     \
    {                                                                                     \
        _Pragma("unroll")                                                                 \
        for (int j = 0; j < 4; j++) {                                                     \
            int idx = tid + 256 * j;                                                      \
            int r = idx >> 3, c = idx & 7;                                                \
            uint32_t da = sb + (buf) * 18432 + r * 144 + c * 16;                          \
            uint32_t db = sb + 36864 + (buf) * 18432 + r * 144 + c * 16;                  \
            CP16(da, A2 + (size_t)(m0 + r) * K2 + (k0) + c * 8);                          \
            CP16(db, B2 + (size_t)(n0 + r) * K2 + (k0) + c * 8);                          \
        }                                                                                 \
        CPCOMMIT();                                                                       \
    }

#define COMPUTE(buf)                                                                      \
    {                                                                                     \
        uint32_t aBase = sb + (buf) * 18432;                                              \
        uint32_t bBase = sb + 36864 + (buf) * 18432;                                      \
        _Pragma("unroll")                                                                 \
        for (int ks = 0; ks < 4; ks++) {                                                  \
            uint32_t af[2][4], bf[4][4];                                                  \
            int kb = ks * 32;                                                             \
            _Pragma("unroll")                                                             \
            for (int i = 0; i < 2; i++) {                                                 \
                uint32_t row = wm + i * 16 + (lane & 15);                                 \
                uint32_t addr = aBase + row * 144 + kb + (lane >> 4) * 16;                \
                ldsm4(addr, af[i][0], af[i][1], af[i][2], af[i][3]);                      \
            }                                                                             \
            _Pragma("unroll")                                                             \
            for (int j = 0; j < 4; j++) {                                                 \
                uint32_t g = lane >> 3, r8 = lane & 7;                                    \
                uint32_t row = wn + j * 16 + ((g >> 1) & 1) * 8 + r8;                     \
                uint32_t addr = bBase + row * 144 + kb + (g & 1) * 16;                    \
                ldsm4(addr, bf[j][0], bf[j][1], bf[j][2], bf[j][3]);                      \
            }                                                                             \
            _Pragma("unroll")                                                             \
            for (int i = 0; i < 2; i++)                                                   \
                _Pragma("unroll")                                                         \
                for (int j = 0; j < 4; j++) {                                             \
                    mma16816(acc[i][2 * j], af[i], &bf[j][0]);                            \
                    mma16816(acc[i][2 * j + 1], af[i], &bf[j][2]);                        \
                }                                                                         \
        }                                                                                 \
    }

    const int nch = K2 >> 6;
    COPY(0, 0);
    for (int ch = 0; ch < nch; ch++) {
        if (ch + 1 < nch) {
            COPY((ch + 1) & 1, (ch + 1) * 64);
            asm volatile("cp.async.wait_group 1;" ::: "memory");
        } else {
            asm volatile("cp.async.wait_group 0;" ::: "memory");
        }
        __syncthreads();
        COMPUTE(ch & 1);
        __syncthreads();
    }

#pragma unroll
    for (int i = 0; i < 2; i++) {
#pragma unroll
        for (int j = 0; j < 8; j++) {
            int m = m0 + wm + i * 16 + (lane >> 2);
            int col = n0 + wn + j * 8 + 2 * (lane & 3);
            if (m < M) {
                float2 v = make_float2(acc[i][j][0], acc[i][j][1]);
                *(float2*)(C + (size_t)m * ldc + col) = v;
            }
            if (m + 8 < M) {
                float2 v = make_float2(acc[i][j][2], acc[i][j][3]);
                *(float2*)(C + (size_t)(m + 8) * ldc + col) = v;
            }
        }
    }
#undef COPY
#undef COMPUTE
}

// ---------------- CSR segmented gather-sum ----------------
__global__ __launch_bounds__(256) void gather_kernel(const float4* __restrict__ msg,
                                                     const int* __restrict__ off,
                                                     const int* __restrict__ csr,
                                                     const float* __restrict__ deg_dst,
                                                     float4* __restrict__ out, int n) {
    int node = blockIdx.x * 4 + (threadIdx.x >> 6);
    int c = threadIdx.x & 63;
    if (node >= n) return;
    int b = off[node], e = off[node + 1];
    float4 acc = make_float4(0.f, 0.f, 0.f, 0.f);
    int i = b;
    for (; i + 4 <= e; i += 4) {
        int s0 = __ldg(&csr[i]), s1 = __ldg(&csr[i + 1]);
        int s2 = __ldg(&csr[i + 2]), s3 = __ldg(&csr[i + 3]);
        float4 v0 = __ldg(&msg[(size_t)s0 * 64 + c]);
        float4 v1 = __ldg(&msg[(size_t)s1 * 64 + c]);
        float4 v2 = __ldg(&msg[(size_t)s2 * 64 + c]);
        float4 v3 = __ldg(&msg[(size_t)s3 * 64 + c]);
        acc.x += v0.x + v1.x + v2.x + v3.x;
        acc.y += v0.y + v1.y + v2.y + v3.y;
        acc.z += v0.z + v1.z + v2.z + v3.z;
        acc.w += v0.w + v1.w + v2.w + v3.w;
    }
    for (; i < e; i++) {
        int s0 = __ldg(&csr[i]);
        float4 v0 = __ldg(&msg[(size_t)s0 * 64 + c]);
        acc.x += v0.x; acc.y += v0.y; acc.z += v0.z; acc.w += v0.w;
    }
    float d = deg_dst[node];
    float sc = d > 0.f ? rsqrtf(d) : 0.f;
    acc.x *= sc; acc.y *= sc; acc.z *= sc; acc.w *= sc;
    out[(size_t)node * 64 + c] = acc;
}

// ---------------- outputs ----------------
__global__ void mean_kernel(const float* __restrict__ s0, const float* __restrict__ s1,
                            const float* __restrict__ s2,
                            const float* __restrict__ u0, const float* __restrict__ u1,
                            const float* __restrict__ u2,
                            float* __restrict__ out, int n) {
    int i = blockIdx.x * blockDim.x + threadIdx.x;
    if (i < n) {
        const float r = 1.f / 3.f;
        out[i] = (fmaxf(s0[i], 0.f) + fmaxf(s1[i], 0.f) + fmaxf(s2[i], 0.f)) * r;
        out[n + i] = (fmaxf(u0[i], 0.f) + fmaxf(u1[i], 0.f) + fmaxf(u2[i], 0.f)) * r;
    }
}

__global__ void out_head_kernel(const float* __restrict__ hs, const float* __restrict__ hu,
                                const float* __restrict__ Ws, const float* __restrict__ bs,
                                const float* __restrict__ Wu, const float* __restrict__ bu,
                                float* __restrict__ out_s, float* __restrict__ out_u) {
    int warp = (blockIdx.x * blockDim.x + threadIdx.x) >> 5;
    int lane = threadIdx.x & 31;
    if (warp < N_SPOT) {
        const float* x = hs + (size_t)warp * HID;
        float s = 0.f;
#pragma unroll
        for (int i = lane; i < HID; i += 32) s += fmaxf(x[i], 0.f) * Ws[i];
#pragma unroll
        for (int o = 16; o; o >>= 1) s += __shfl_down_sync(0xffffffffu, s, o);
        if (lane == 0) out_s[warp] = s + bs[0];
    } else if (warp < 2 * N_SPOT) {
        int n = warp - N_SPOT;
        const float* x = hu + (size_t)n * HID;
        float s = 0.f;
#pragma unroll
        for (int i = lane; i < HID; i += 32) s += fmaxf(x[i], 0.f) * Wu[i];
#pragma unroll
        for (int o = 16; o; o >>= 1) s += __shfl_down_sync(0xffffffffu, s, o);
        if (lane == 0) out_u[n] = s + bu[0];
    }
}

// ---------------- host ----------------
static float* sym_addr(const void* sym) {
    void* p = nullptr;
    cudaGetSymbolAddress(&p, sym);
    return (float*)p;
}
static int* sym_addr_i(const void* sym) {
    void* p = nullptr;
    cudaGetSymbolAddress(&p, sym);
    return (int*)p;
}
static __nv_bfloat16* sym_addr_b(const void* sym) {
    void* p = nullptr;
    cudaGetSymbolAddress(&p, sym);
    return (__nv_bfloat16*)p;
}

extern "C" void kernel_launch(void* const* d_in, const int* in_sizes, int n_in,
                              void* d_out, int out_size) {
    const float* x_spot  = (const float*)d_in[0];
    const float* x_user  = (const float*)d_in[1];
    const int*   edge_us = (const int*)d_in[2];
    const int*   edge_su = (const int*)d_in[3];
    const float* W_att   = (const float*)d_in[4];
    const float* q_att   = (const float*)d_in[5];
    const float* W0_us   = (const float*)d_in[6];
    const float* W0_su   = (const float*)d_in[7];
    const float* Wmid_us = (const float*)d_in[8];
    const float* Wmid_su = (const float*)d_in[9];
    const float* W_out_s = (const float*)d_in[10];
    const float* b_out_s = (const float*)d_in[11];
    const float* W_out_u = (const float*)d_in[12];
    const float* b_out_u = (const float*)d_in[13];
    float* out = (float*)d_out;

    float* p_wq    = sym_addr(g_wq);
    float* p_xs    = sym_addr(g_xs);
    float* p_tmp_u = sym_addr(g_tmp_u);
    float* p_tmp_s = sym_addr(g_tmp_s);
    float* p_hs    = sym_addr(g_hs);
    float* p_hu    = sym_addr(g_hu);
    float* p_deg   = sym_addr(g_deg);
    int* p_off_us  = sym_addr_i(g_off_us);
    int* p_cur_us  = sym_addr_i(g_cur_us);
    int* p_csr_us  = sym_addr_i(g_csr_us);
    int* p_off_su  = sym_addr_i(g_off_su);
    int* p_cur_su  = sym_addr_i(g_cur_su);
    int* p_csr_su  = sym_addr_i(g_csr_su);
    __nv_bfloat16* p_A2att = sym_addr_b(g_A2att);
    __nv_bfloat16* p_Au2   = sym_addr_b(g_Au2);
    __nv_bfloat16* p_As2   = sym_addr_b(g_As2);
    __nv_bfloat16* p_B2    = sym_addr_b(g_B2);

    const size_t HN = (size_t)N_SPOT * HID;
    const int NHID = N_SPOT * HID;
    const int SMEM = 73728;
    cudaFuncSetAttribute(hmma_gemm, cudaFuncAttributeMaxDynamicSharedMemorySize, SMEM);

    // degrees
    cudaMemsetAsync(p_deg, 0, 4 * N_SPOT * sizeof(float));
    int eb = (NE + 255) / 256;
    deg_count_kernel<<<eb, 256>>>(edge_us, edge_su, p_deg);

    // CSR build (by destination)
    scan_kernel<<<1, 1024>>>(p_deg + 1 * N_SPOT, p_off_us, p_cur_us, N_SPOT);
    scan_kernel<<<1, 1024>>>(p_deg + 3 * N_SPOT, p_off_su, p_cur_su, N_USER);
    fill_kernel<<<eb, 256>>>(edge_us, edge_us + NE, p_cur_us, p_csr_us, NE);
    fill_kernel<<<eb, 256>>>(edge_su, edge_su + NE, p_cur_su, p_csr_su, NE);

    // weights: transpose + split
    for (int h = 0; h < HEADS; h++)
        wprep_kernel<<<(128 * 512 + 255) / 256, 256>>>(
            W_att + (size_t)h * ATT_IN * PER, ATT_IN, PER, p_B2 + WOFF_ATT + h * 128 * 1536);
    wprep_kernel<<<(256 * 512 + 255) / 256, 256>>>(W0_us, 512, HID, p_B2 + WOFF_L0US);
    wprep_kernel<<<(256 * 512 + 255) / 256, 256>>>(W0_su, 512, HID, p_B2 + WOFF_L0SU);
    for (int l = 0; l < 2; l++) {
        wprep_kernel<<<(256 * 256 + 255) / 256, 256>>>(
            Wmid_us + (size_t)l * HID * HID, HID, HID, p_B2 + WOFF_MUS + l * 256 * 768);
        wprep_kernel<<<(256 * 256 + 255) / 256, 256>>>(
            Wmid_su + (size_t)l * HID * HID, HID, HID, p_B2 + WOFF_MSU + l * 256 * 768);
    }

    // attention pooling -> split A
    wq_kernel<<<(HEADS * ATT_IN + 255) / 256, 256>>>(W_att, q_att, p_wq);
    att_kernel<<<MPAD, 128>>>(x_spot, p_wq, p_A2att);
    // xs[:, h*128:(h+1)*128] = Y[h] @ W_att[h]
    hmma_gemm<<<dim3(MPAD / 128, 1, HEADS), 256, SMEM>>>(
        p_A2att, p_B2 + WOFF_ATT, p_xs, ATT_IN, N_SPOT, 1536,
        (long)MPAD * 1536, (long)128 * 1536, (long)PER);

    int gb = (N_SPOT + 3) / 4;
    int rb = (NHID + 255) / 256;

    // ---- layer 0 (src norm folded into aconv) ----
    aconv_kernel<<<(MPAD * 128 + 255) / 256, 256>>>(
        (const float4*)x_user, p_deg + 0 * N_SPOT, 0, N_USER, 128, MPAD,
        (__nv_bfloat162*)p_Au2);
    aconv_kernel<<<(MPAD * 128 + 255) / 256, 256>>>(
        (const float4*)p_xs, p_deg + 2 * N_SPOT, 0, N_SPOT, 128, MPAD,
        (__nv_bfloat162*)p_As2);
    hmma_gemm<<<dim3(MPAD / 128, 2, 1), 256, SMEM>>>(
        p_Au2, p_B2 + WOFF_L0US, p_tmp_u, HID, N_USER, 1536, 0, 0, 0);
    hmma_gemm<<<dim3(MPAD / 128, 2, 1), 256, SMEM>>>(
        p_As2, p_B2 + WOFF_L0SU, p_tmp_s, HID, N_SPOT, 1536, 0, 0, 0);
    gather_kernel<<<gb, 256>>>((const float4*)p_tmp_u, p_off_us, p_csr_us,
                               p_deg + 1 * N_SPOT, (float4*)p_hs, N_SPOT);
    gather_kernel<<<gb, 256>>>((const float4*)p_tmp_s, p_off_su, p_csr_su,
                               p_deg + 3 * N_SPOT, (float4*)p_hu, N_USER);

    // ---- layers 1 & 2 (ReLU + src norm in aconv) ----
    for (int l = 1; l < 3; l++) {
        float* hs_prev = p_hs + (l - 1) * HN;
        float* hu_prev = p_hu + (l - 1) * HN;
        float* hs_new  = p_hs + l * HN;
        float* hu_new  = p_hu + l * HN;
        aconv_kernel<<<(MPAD * 64 + 255) / 256, 256>>>(
            (const float4*)hu_prev, p_deg + 0 * N_SPOT, 1, N_USER, 64, MPAD,
            (__nv_bfloat162*)p_Au2);
        aconv_kernel<<<(MPAD * 64 + 255) / 256, 256>>>(
            (const float4*)hs_prev, p_deg + 2 * N_SPOT, 1, N_SPOT, 64, MPAD,
            (__nv_bfloat162*)p_As2);
        hmma_gemm<<<dim3(MPAD / 128, 2, 1), 256, SMEM>>>(
            p_Au2, p_B2 + WOFF_MUS + (l - 1) * 256 * 768, p_tmp_u, HID, N_USER, 768, 0, 0, 0);
        hmma_gemm<<<dim3(MPAD / 128, 2, 1), 256, SMEM>>>(
            p_As2, p_B2 + WOFF_MSU + (l - 1) * 256 * 768, p_tmp_s, HID, N_SPOT, 768, 0, 0, 0);
        gather_kernel<<<gb, 256>>>((const float4*)p_tmp_u, p_off_us, p_csr_us,
                                   p_deg + 1 * N_SPOT, (float4*)hs_new, N_SPOT);
        gather_kernel<<<gb, 256>>>((const float4*)p_tmp_s, p_off_su, p_csr_su,
                                   p_deg + 3 * N_SPOT, (float4*)hu_new, N_USER);
    }

    // ---- outputs ----
    mean_kernel<<<rb, 256>>>(p_hs, p_hs + HN, p_hs + 2 * HN,
                             p_hu, p_hu + HN, p_hu + 2 * HN, out, NHID);
    out_head_kernel<<<(2 * N_SPOT * 32 + 255) / 256, 256>>>(
        p_hs + 2 * HN, p_hu + 2 * HN, W_out_s, b_out_s, W_out_u, b_out_u,
        out + 2 * (size_t)NHID, out + 2 * (size_t)NHID + N_SPOT);
}

// round 8
// speedup vs baseline: 3.4052x; 1.0430x over previous
#include <cuda_runtime.h>
#include <cuda_bf16.h>
#include <cstdint>

#define N_SPOT 30000
#define N_USER 30000
#define NE     600000
#define SPLIT  5
#define ATT_IN 512
#define HEADS  4
#define PER    128
#define HID    256
#define MPAD   30080   // 235 * 128

// ---------------- scratch (device globals; no allocation) ----------------
__device__ float g_wq[HEADS * ATT_IN];
__device__ float g_tmp_u[(size_t)N_USER * HID];
__device__ float g_tmp_s[(size_t)N_SPOT * HID];
__device__ float g_hs[3][(size_t)N_SPOT * HID];
__device__ float g_hu[3][(size_t)N_USER * HID];
__device__ float g_deg[4 * N_SPOT];
__device__ int   g_off_us[N_SPOT + 1];
__device__ int   g_cur_us[N_SPOT];
__device__ int   g_csr_us[NE];
__device__ int   g_off_su[N_USER + 1];
__device__ int   g_cur_su[N_USER];
__device__ int   g_csr_su[NE];

// bf16 2-block split operands along K: [Ah | Al]  (row length = 2K)
__device__ __nv_bfloat16 g_A2att[(size_t)HEADS * MPAD * 1024];  // att: K=512
__device__ __nv_bfloat16 g_Au2[(size_t)MPAD * 1024];
__device__ __nv_bfloat16 g_As2[(size_t)MPAD * 1024];
// weights transposed [N][2K] as [Bh | Bl]
#define WOFF_ATT   0
#define WOFF_L0US  (4 * 128 * 1024)
#define WOFF_L0SU  (WOFF_L0US + 256 * 1024)
#define WOFF_MUS   (WOFF_L0SU + 256 * 1024)
#define WOFF_MSU   (WOFF_MUS + 2 * 256 * 512)
#define WTOT       (WOFF_MSU + 2 * 256 * 512)
__device__ __nv_bfloat16 g_B2[WTOT];

// ---------------- helpers ----------------
__device__ __forceinline__ uint32_t smem_u32(const void* p) {
    uint32_t r;
    asm("{ .reg .u64 t; cvta.to.shared.u64 t, %1; cvt.u32.u64 %0, t; }" : "=r"(r) : "l"(p));
    return r;
}
__device__ __forceinline__ void ldsm4(uint32_t addr, uint32_t& r0, uint32_t& r1,
                                      uint32_t& r2, uint32_t& r3) {
    asm volatile("ldmatrix.sync.aligned.m8n8.x4.shared.b16 {%0,%1,%2,%3}, [%4];"
                 : "=r"(r0), "=r"(r1), "=r"(r2), "=r"(r3) : "r"(addr));
}
__device__ __forceinline__ void mma16816(float* d, const uint32_t* a, const uint32_t* b) {
    asm volatile(
        "mma.sync.aligned.m16n8k16.row.col.f32.bf16.bf16.f32 "
        "{%0,%1,%2,%3}, {%4,%5,%6,%7}, {%8,%9}, {%0,%1,%2,%3};"
        : "+f"(d[0]), "+f"(d[1]), "+f"(d[2]), "+f"(d[3])
        : "r"(a[0]), "r"(a[1]), "r"(a[2]), "r"(a[3]), "r"(b[0]), "r"(b[1]));
}
#define CP16(dst, src) \
    asm volatile("cp.async.ca.shared.global [%0], [%1], 16;" :: "r"(dst), "l"(src))
#define CPCOMMIT() asm volatile("cp.async.commit_group;" ::: "memory")

// ---------------- degree ----------------
__global__ void deg_count_kernel(const int* __restrict__ e_us, const int* __restrict__ e_su,
                                 float* __restrict__ deg) {
    int i = blockIdx.x * blockDim.x + threadIdx.x;
    if (i < NE) {
        atomicAdd(&deg[0 * N_SPOT + e_us[i]], 1.0f);
        atomicAdd(&deg[1 * N_SPOT + e_us[NE + i]], 1.0f);
        atomicAdd(&deg[2 * N_SPOT + e_su[i]], 1.0f);
        atomicAdd(&deg[3 * N_SPOT + e_su[NE + i]], 1.0f);
    }
}

// ---------------- CSR build ----------------
__global__ __launch_bounds__(1024) void scan_kernel(const float* __restrict__ deg,
                                                    int* __restrict__ off,
                                                    int* __restrict__ cur, int n) {
    __shared__ int part[1024];
    const int t = threadIdx.x;
    const int CH = (n + 1023) / 1024;
    const int base = t * CH;
    int s = 0;
    for (int j = 0; j < CH; j++) {
        int idx = base + j;
        if (idx < n) s += (int)deg[idx];
    }
    part[t] = s;
    __syncthreads();
    for (int o = 1; o < 1024; o <<= 1) {
        int v = (t >= o) ? part[t - o] : 0;
        __syncthreads();
        part[t] += v;
        __syncthreads();
    }
    int run = t ? part[t - 1] : 0;
    for (int j = 0; j < CH; j++) {
        int idx = base + j;
        if (idx < n) {
            off[idx] = run;
            cur[idx] = run;
            run += (int)deg[idx];
        }
    }
    if (t == 0) off[n] = part[1023];
}

__global__ void fill_kernel(const int* __restrict__ src, const int* __restrict__ dst,
                            int* __restrict__ cur, int* __restrict__ csr, int n) {
    int e = blockIdx.x * blockDim.x + threadIdx.x;
    if (e < n) {
        int p = atomicAdd(&cur[dst[e]], 1);
        csr[p] = src[e];
    }
}

// ---------------- weight transpose + split: W[K,N] -> B2[N][2K] = [Bh|Bl] ----------------
__global__ void wprep_kernel(const float* __restrict__ W, int K, int N,
                             __nv_bfloat16* __restrict__ B2) {
    int idx = blockIdx.x * 256 + threadIdx.x;
    if (idx >= N * K) return;
    int n = idx / K, k = idx % K;
    float v = W[(size_t)k * N + n];
    __nv_bfloat16 h = __float2bfloat16(v);
    float r = v - __bfloat162float(h);
    size_t base = (size_t)n * 2 * K;
    B2[base + k] = h;
    B2[base + K + k] = __float2bfloat16(r);
}

// ---------------- fp32 -> A2[M][2K] = [Ah|Al] with row scale (layer-0 user) ------------
__global__ void aconv_kernel(const float4* __restrict__ in, const float* __restrict__ deg,
                             int M, int Kq, int Mpad,
                             __nv_bfloat162* __restrict__ out2) {
    int idx = blockIdx.x * 256 + threadIdx.x;
    if (idx >= Mpad * Kq) return;
    int row = idx / Kq, q = idx - row * Kq;
    const int K = Kq * 4;
    float4 v = make_float4(0.f, 0.f, 0.f, 0.f);
    if (row < M) {
        v = in[idx];
        float d = deg[row];
        float sc = d > 0.f ? rsqrtf(d) : 0.f;
        v.x *= sc; v.y *= sc; v.z *= sc; v.w *= sc;
    }
    __nv_bfloat16 hx = __float2bfloat16(v.x), hy = __float2bfloat16(v.y);
    __nv_bfloat16 hz = __float2bfloat16(v.z), hw = __float2bfloat16(v.w);
    float rx = v.x - __bfloat162float(hx), ry = v.y - __bfloat162float(hy);
    float rz = v.z - __bfloat162float(hz), rw = v.w - __bfloat162float(hw);
    size_t b2 = (size_t)row * K;  // bf162 units per row = K
    out2[b2 + 2 * q + 0] = __nv_bfloat162(hx, hy);
    out2[b2 + 2 * q + 1] = __nv_bfloat162(hz, hw);
    out2[b2 + K / 2 + 2 * q + 0] = __nv_bfloat162(__float2bfloat16(rx), __float2bfloat16(ry));
    out2[b2 + K / 2 + 2 * q + 1] = __nv_bfloat162(__float2bfloat16(rz), __float2bfloat16(rw));
}

// ---------------- attention ----------------
__global__ void wq_kernel(const float* __restrict__ W, const float* __restrict__ q,
                          float* __restrict__ wq) {
    int t = blockIdx.x * blockDim.x + threadIdx.x;
    if (t >= HEADS * ATT_IN) return;
    int h = t / ATT_IN, i = t % ATT_IN;
    const float* w = W + ((size_t)h * ATT_IN + i) * PER;
    const float* qq = q + h * PER;
    float s = 0.f;
#pragma unroll 8
    for (int p = 0; p < PER; p++) s += w[p] * qq[p];
    wq[t] = s;
}

// per node: softmax pooling; emits [hi(512) | lo(512)] per head row.
__global__ __launch_bounds__(128) void att_kernel(const float* __restrict__ x,
                                                  const float* __restrict__ wq,
                                                  __nv_bfloat16* __restrict__ A2) {
    int n = blockIdx.x;
    if (n >= N_SPOT) {
        __nv_bfloat16 z = __float2bfloat16(0.f);
        for (int h = 0; h < HEADS; h++)
            for (int i = threadIdx.x; i < 1024; i += 128)
                A2[((size_t)h * MPAD + n) * 1024 + i] = z;
        return;
    }
    __shared__ float sx[SPLIT * ATT_IN];
    __shared__ float satt[HEADS][SPLIT];
    const float* xr = x + (size_t)n * (SPLIT * ATT_IN);
    for (int i = threadIdx.x; i < SPLIT * ATT_IN; i += 128) sx[i] = xr[i];
    __syncthreads();

    int w = threadIdx.x >> 5, lane = threadIdx.x & 31;
    if (w < HEADS) {
        float lg[SPLIT];
#pragma unroll
        for (int s = 0; s < SPLIT; s++) {
            float p = 0.f;
            for (int i = lane; i < ATT_IN; i += 32) p += sx[s * ATT_IN + i] * wq[w * ATT_IN + i];
#pragma unroll
            for (int o = 16; o; o >>= 1) p += __shfl_down_sync(0xffffffffu, p, o);
            lg[s] = p;
        }
        if (lane == 0) {
            float mx = -1e30f;
#pragma unroll
            for (int s = 0; s < SPLIT; s++) {
                lg[s] = lg[s] >= 0.f ? lg[s] : 0.2f * lg[s];
                mx = fmaxf(mx, lg[s]);
            }
            float sum = 0.f;
#pragma unroll
            for (int s = 0; s < SPLIT; s++) { lg[s] = expf(lg[s] - mx); sum += lg[s]; }
            float r = 1.f / sum;
#pragma unroll
            for (int s = 0; s < SPLIT; s++) satt[w][s] = lg[s] * r;
        }
    }
    __syncthreads();

#pragma unroll
    for (int h = 0; h < HEADS; h++) {
        float a0 = satt[h][0], a1 = satt[h][1], a2 = satt[h][2], a3 = satt[h][3], a4 = satt[h][4];
        for (int i = threadIdx.x; i < ATT_IN; i += 128) {
            float y = a0 * sx[i] + a1 * sx[ATT_IN + i] + a2 * sx[2 * ATT_IN + i]
                    + a3 * sx[3 * ATT_IN + i] + a4 * sx[4 * ATT_IN + i];
            __nv_bfloat16 hh = __float2bfloat16(y);
            float r = y - __bfloat162float(hh);
            size_t base = ((size_t)h * MPAD + n) * 1024;
            A2[base + i] = hh;
            A2[base + 512 + i] = __float2bfloat16(r);
        }
    }
}

// ---------------- bf16 HMMA GEMM with 3-product split schedule ----------------
// A stored [M][2K]=[Ah|Al], B stored [N][2K]=[Bh|Bl].
// Per K-slice rem: Ah(rem)*Bh(rem), Al(rem)*Bh(rem), Ah(rem)*Bl(rem).
// EPI=0: C fp32 [M][ldc]. EPI=1: split-bf16 out [M][ldc(bf16)] = [hi|lo], scaled rsqrt(deg).
template <int EPI>
__global__ __launch_bounds__(256, 2) void hmma_gemm(
    const __nv_bfloat16* __restrict__ A2, int lda,
    const __nv_bfloat16* __restrict__ B2, int ldb,
    float* __restrict__ C, __nv_bfloat162* __restrict__ outb,
    const float* __restrict__ degp,
    int ldc, int M, int K,
    long sA, long sB, long sC) {
    extern __shared__ __align__(16) char smem[];
    uint32_t sb = smem_u32(smem);
    const int tid = threadIdx.x;
    const int wid = tid >> 5, lane = tid & 31;
    A2 += (long)blockIdx.z * sA;
    B2 += (long)blockIdx.z * sB;
    int col0 = 0;
    if (EPI == 0) C += (long)blockIdx.z * sC;
    else col0 = (int)((long)blockIdx.z * sC);
    const int m0 = blockIdx.x * 128;
    const int n0 = blockIdx.y * 128;
    const int wm = (wid & 3) * 32;
    const int wn = (wid >> 2) * 64;

    float acc[2][8][4];
#pragma unroll
    for (int i = 0; i < 2; i++)
#pragma unroll
        for (int j = 0; j < 8; j++)
#pragma unroll
            for (int v = 0; v < 4; v++) acc[i][j][v] = 0.f;

#define OFFS(ch, ka, kb)                                   \
    {                                                      \
        int bq = (ch) / 3, br_ = (ch) - 3 * bq;            \
        ka = bq * 64 + (br_ == 1 ? K : 0);                 \
        kb = bq * 64 + (br_ == 2 ? K : 0);                 \
    }

#define COPY(buf, ka, kb)                                                                 \
    {                                                                                     \
        _Pragma("unroll")                                                                 \
        for (int j = 0; j < 4; j++) {                                                     \
            int idx = tid + 256 * j;                                                      \
            int r = idx >> 3, c = idx & 7;                                                \
            uint32_t da = sb + (buf) * 18432 + r * 144 + c * 16;                          \
            uint32_t db = sb + 36864 + (buf) * 18432 + r * 144 + c * 16;                  \
            CP16(da, A2 + (size_t)(m0 + r) * lda + (ka) + c * 8);                         \
            CP16(db, B2 + (size_t)(n0 + r) * ldb + (kb) + c * 8);                         \
        }                                                                                 \
        CPCOMMIT();                                                                       \
    }

#define COMPUTE(buf)                                                                      \
    {                                                                                     \
        uint32_t aBase = sb + (buf) * 18432;                                              \
        uint32_t bBase = sb + 36864 + (buf) * 18432;                                      \
        _Pragma("unroll")                                                                 \
        for (int ks = 0; ks < 4; ks++) {                                                  \
            uint32_t af[2][4], bf[4][4];                                                  \
            int kb_ = ks * 32;                                                            \
            _Pragma("unroll")                                                             \
            for (int i = 0; i < 2; i++) {                                                 \
                uint32_t row = wm + i * 16 + (lane & 15);                                 \
                uint32_t addr = aBase + row * 144 + kb_ + (lane >> 4) * 16;               \
                ldsm4(addr, af[i][0], af[i][1], af[i][2], af[i][3]);                      \
            }                                                                             \
            _Pragma("unroll")                                                             \
            for (int j = 0; j < 4; j++) {                                                 \
                uint32_t g = lane >> 3, r8 = lane & 7;                                    \
                uint32_t row = wn + j * 16 + ((g >> 1) & 1) * 8 + r8;                     \
                uint32_t addr = bBase + row * 144 + kb_ + (g & 1) * 16;                   \
                ldsm4(addr, bf[j][0], bf[j][1], bf[j][2], bf[j][3]);                      \
            }                                                                             \
            _Pragma("unroll")                                                             \
            for (int i = 0; i < 2; i++)                                                   \
                _Pragma("unroll")                                                         \
                for (int j = 0; j < 4; j++) {                                             \
                    mma16816(acc[i][2 * j], af[i], &bf[j][0]);                            \
                    mma16816(acc[i][2 * j + 1], af[i], &bf[j][2]);                        \
                }                                                                         \
        }                                                                                 \
    }

    const int nch = 3 * (K >> 6);
    {
        int ka, kb;
        OFFS(0, ka, kb);
        COPY(0, ka, kb);
    }
    for (int ch = 0; ch < nch; ch++) {
        if (ch + 1 < nch) {
            int ka, kb;
            OFFS(ch + 1, ka, kb);
            COPY((ch + 1) & 1, ka, kb);
            asm volatile("cp.async.wait_group 1;" ::: "memory");
        } else {
            asm volatile("cp.async.wait_group 0;" ::: "memory");
        }
        __syncthreads();
        COMPUTE(ch & 1);
        __syncthreads();
    }

#pragma unroll
    for (int i = 0; i < 2; i++) {
#pragma unroll
        for (int j = 0; j < 8; j++) {
            int mA = m0 + wm + i * 16 + (lane >> 2);
            int col = n0 + wn + j * 8 + 2 * (lane & 3);
            if (EPI == 0) {
                if (mA < M) {
                    float2 v = make_float2(acc[i][j][0], acc[i][j][1]);
                    *(float2*)(C + (size_t)mA * ldc + col) = v;
                }
                if (mA + 8 < M) {
                    float2 v = make_float2(acc[i][j][2], acc[i][j][3]);
                    *(float2*)(C + (size_t)(mA + 8) * ldc + col) = v;
                }
            } else {
#pragma unroll
                for (int hh = 0; hh < 2; hh++) {
                    int m = mA + 8 * hh;
                    if (m < M) {
                        float d = degp[m];
                        float sc = d > 0.f ? rsqrtf(d) : 0.f;
                        float v0 = acc[i][j][2 * hh] * sc;
                        float v1 = acc[i][j][2 * hh + 1] * sc;
                        __nv_bfloat16 h0 = __float2bfloat16(v0);
                        __nv_bfloat16 h1 = __float2bfloat16(v1);
                        float l0 = v0 - __bfloat162float(h0);
                        float l1 = v1 - __bfloat162float(h1);
                        size_t base = (size_t)m * ldc + col0 + col;
                        outb[base >> 1] = __nv_bfloat162(h0, h1);
                        outb[(base + (ldc >> 1)) >> 1] =
                            __nv_bfloat162(__float2bfloat16(l0), __float2bfloat16(l1));
                    }
                }
            }
        }
    }
#undef OFFS
#undef COPY
#undef COMPUTE
}

// ---------------- CSR segmented gather-sum (+ fused split-bf16 A2 emit) ----------------
__global__ __launch_bounds__(256) void gather_kernel(const float4* __restrict__ msg,
                                                     const int* __restrict__ off,
                                                     const int* __restrict__ csr,
                                                     const float* __restrict__ deg_dst,
                                                     float4* __restrict__ out, int n,
                                                     __nv_bfloat162* __restrict__ a2out,
                                                     const float* __restrict__ deg_src) {
    int node = blockIdx.x * 4 + (threadIdx.x >> 6);
    int c = threadIdx.x & 63;
    if (node >= n) return;
    int b = off[node], e = off[node + 1];
    float4 acc = make_float4(0.f, 0.f, 0.f, 0.f);
    int i = b;
    for (; i + 4 <= e; i += 4) {
        int s0 = __ldg(&csr[i]), s1 = __ldg(&csr[i + 1]);
        int s2 = __ldg(&csr[i + 2]), s3 = __ldg(&csr[i + 3]);
        float4 v0 = __ldg(&msg[(size_t)s0 * 64 + c]);
        float4 v1 = __ldg(&msg[(size_t)s1 * 64 + c]);
        float4 v2 = __ldg(&msg[(size_t)s2 * 64 + c]);
        float4 v3 = __ldg(&msg[(size_t)s3 * 64 + c]);
        acc.x += v0.x + v1.x + v2.x + v3.x;
        acc.y += v0.y + v1.y + v2.y + v3.y;
        acc.z += v0.z + v1.z + v2.z + v3.z;
        acc.w += v0.w + v1.w + v2.w + v3.w;
    }
    for (; i < e; i++) {
        int s0 = __ldg(&csr[i]);
        float4 v0 = __ldg(&msg[(size_t)s0 * 64 + c]);
        acc.x += v0.x; acc.y += v0.y; acc.z += v0.z; acc.w += v0.w;
    }
    float d = deg_dst[node];
    float sc = d > 0.f ? rsqrtf(d) : 0.f;
    acc.x *= sc; acc.y *= sc; acc.z *= sc; acc.w *= sc;
    out[(size_t)node * 64 + c] = acc;

    if (a2out) {
        float d2 = deg_src[node];
        float s2c = d2 > 0.f ? rsqrtf(d2) : 0.f;
        float vx = fmaxf(acc.x, 0.f) * s2c, vy = fmaxf(acc.y, 0.f) * s2c;
        float vz = fmaxf(acc.z, 0.f) * s2c, vw = fmaxf(acc.w, 0.f) * s2c;
        __nv_bfloat16 hx = __float2bfloat16(vx), hy = __float2bfloat16(vy);
        __nv_bfloat16 hz = __float2bfloat16(vz), hw = __float2bfloat16(vw);
        float rx = vx - __bfloat162float(hx), ry = vy - __bfloat162float(hy);
        float rz = vz - __bfloat162float(hz), rw = vw - __bfloat162float(hw);
        size_t bb = (size_t)node * 256 + 2 * c;  // row = 512 bf16 = 256 bf162
        a2out[bb + 0] = __nv_bfloat162(hx, hy);
        a2out[bb + 1] = __nv_bfloat162(hz, hw);
        a2out[bb + 128 + 0] = __nv_bfloat162(__float2bfloat16(rx), __float2bfloat16(ry));
        a2out[bb + 128 + 1] = __nv_bfloat162(__float2bfloat16(rz), __float2bfloat16(rw));
    }
}

// ---------------- outputs ----------------
__global__ void mean_kernel(const float* __restrict__ s0, const float* __restrict__ s1,
                            const float* __restrict__ s2,
                            const float* __restrict__ u0, const float* __restrict__ u1,
                            const float* __restrict__ u2,
                            float* __restrict__ out, int n) {
    int i = blockIdx.x * blockDim.x + threadIdx.x;
    if (i < n) {
        const float r = 1.f / 3.f;
        out[i] = (fmaxf(s0[i], 0.f) + fmaxf(s1[i], 0.f) + fmaxf(s2[i], 0.f)) * r;
        out[n + i] = (fmaxf(u0[i], 0.f) + fmaxf(u1[i], 0.f) + fmaxf(u2[i], 0.f)) * r;
    }
}

__global__ void out_head_kernel(const float* __restrict__ hs, const float* __restrict__ hu,
                                const float* __restrict__ Ws, const float* __restrict__ bs,
                                const float* __restrict__ Wu, const float* __restrict__ bu,
                                float* __restrict__ out_s, float* __restrict__ out_u) {
    int warp = (blockIdx.x * blockDim.x + threadIdx.x) >> 5;
    int lane = threadIdx.x & 31;
    if (warp < N_SPOT) {
        const float* x = hs + (size_t)warp * HID;
        float s = 0.f;
#pragma unroll
        for (int i = lane; i < HID; i += 32) s += fmaxf(x[i], 0.f) * Ws[i];
#pragma unroll
        for (int o = 16; o; o >>= 1) s += __shfl_down_sync(0xffffffffu, s, o);
        if (lane == 0) out_s[warp] = s + bs[0];
    } else if (warp < 2 * N_SPOT) {
        int n = warp - N_SPOT;
        const float* x = hu + (size_t)n * HID;
        float s = 0.f;
#pragma unroll
        for (int i = lane; i < HID; i += 32) s += fmaxf(x[i], 0.f) * Wu[i];
#pragma unroll
        for (int o = 16; o; o >>= 1) s += __shfl_down_sync(0xffffffffu, s, o);
        if (lane == 0) out_u[n] = s + bu[0];
    }
}

// ---------------- host ----------------
static float* sym_addr(const void* sym) {
    void* p = nullptr;
    cudaGetSymbolAddress(&p, sym);
    return (float*)p;
}
static int* sym_addr_i(const void* sym) {
    void* p = nullptr;
    cudaGetSymbolAddress(&p, sym);
    return (int*)p;
}
static __nv_bfloat16* sym_addr_b(const void* sym) {
    void* p = nullptr;
    cudaGetSymbolAddress(&p, sym);
    return (__nv_bfloat16*)p;
}

extern "C" void kernel_launch(void* const* d_in, const int* in_sizes, int n_in,
                              void* d_out, int out_size) {
    const float* x_spot  = (const float*)d_in[0];
    const float* x_user  = (const float*)d_in[1];
    const int*   edge_us = (const int*)d_in[2];
    const int*   edge_su = (const int*)d_in[3];
    const float* W_att   = (const float*)d_in[4];
    const float* q_att   = (const float*)d_in[5];
    const float* W0_us   = (const float*)d_in[6];
    const float* W0_su   = (const float*)d_in[7];
    const float* Wmid_us = (const float*)d_in[8];
    const float* Wmid_su = (const float*)d_in[9];
    const float* W_out_s = (const float*)d_in[10];
    const float* b_out_s = (const float*)d_in[11];
    const float* W_out_u = (const float*)d_in[12];
    const float* b_out_u = (const float*)d_in[13];
    float* out = (float*)d_out;

    float* p_wq    = sym_addr(g_wq);
    float* p_tmp_u = sym_addr(g_tmp_u);
    float* p_tmp_s = sym_addr(g_tmp_s);
    float* p_hs    = sym_addr(g_hs);
    float* p_hu    = sym_addr(g_hu);
    float* p_deg   = sym_addr(g_deg);
    int* p_off_us  = sym_addr_i(g_off_us);
    int* p_cur_us  = sym_addr_i(g_cur_us);
    int* p_csr_us  = sym_addr_i(g_csr_us);
    int* p_off_su  = sym_addr_i(g_off_su);
    int* p_cur_su  = sym_addr_i(g_cur_su);
    int* p_csr_su  = sym_addr_i(g_csr_su);
    __nv_bfloat16* p_A2att = sym_addr_b(g_A2att);
    __nv_bfloat16* p_Au2   = sym_addr_b(g_Au2);
    __nv_bfloat16* p_As2   = sym_addr_b(g_As2);
    __nv_bfloat16* p_B2    = sym_addr_b(g_B2);

    const size_t HN = (size_t)N_SPOT * HID;
    const int NHID = N_SPOT * HID;
    const int SMEM = 73728;
    cudaFuncSetAttribute(hmma_gemm<0>, cudaFuncAttributeMaxDynamicSharedMemorySize, SMEM);
    cudaFuncSetAttribute(hmma_gemm<1>, cudaFuncAttributeMaxDynamicSharedMemorySize, SMEM);

    // degrees
    cudaMemsetAsync(p_deg, 0, 4 * N_SPOT * sizeof(float));
    int eb = (NE + 255) / 256;
    deg_count_kernel<<<eb, 256>>>(edge_us, edge_su, p_deg);

    // CSR build (by destination)
    scan_kernel<<<1, 1024>>>(p_deg + 1 * N_SPOT, p_off_us, p_cur_us, N_SPOT);
    scan_kernel<<<1, 1024>>>(p_deg + 3 * N_SPOT, p_off_su, p_cur_su, N_USER);
    fill_kernel<<<eb, 256>>>(edge_us, edge_us + NE, p_cur_us, p_csr_us, NE);
    fill_kernel<<<eb, 256>>>(edge_su, edge_su + NE, p_cur_su, p_csr_su, NE);

    // weights: transpose + split
    for (int h = 0; h < HEADS; h++)
        wprep_kernel<<<(128 * 512 + 255) / 256, 256>>>(
            W_att + (size_t)h * ATT_IN * PER, ATT_IN, PER, p_B2 + WOFF_ATT + h * 128 * 1024);
    wprep_kernel<<<(256 * 512 + 255) / 256, 256>>>(W0_us, 512, HID, p_B2 + WOFF_L0US);
    wprep_kernel<<<(256 * 512 + 255) / 256, 256>>>(W0_su, 512, HID, p_B2 + WOFF_L0SU);
    for (int l = 0; l < 2; l++) {
        wprep_kernel<<<(256 * 256 + 255) / 256, 256>>>(
            Wmid_us + (size_t)l * HID * HID, HID, HID, p_B2 + WOFF_MUS + l * 256 * 512);
        wprep_kernel<<<(256 * 256 + 255) / 256, 256>>>(
            Wmid_su + (size_t)l * HID * HID, HID, HID, p_B2 + WOFF_MSU + l * 256 * 512);
    }

    // attention pooling -> split A (2-block)
    wq_kernel<<<(HEADS * ATT_IN + 255) / 256, 256>>>(W_att, q_att, p_wq);
    att_kernel<<<MPAD, 128>>>(x_spot, p_wq, p_A2att);
    // att GEMM writes layer-0 spot A operand directly (split-bf16, scaled by spot src-norm)
    hmma_gemm<1><<<dim3(MPAD / 128, 1, HEADS), 256, SMEM>>>(
        p_A2att, 1024, p_B2 + WOFF_ATT, 1024, nullptr,
        (__nv_bfloat162*)p_As2, p_deg + 2 * N_SPOT,
        1024, N_SPOT, 512,
        (long)MPAD * 1024, (long)128 * 1024, 128);

    int gb = (N_SPOT + 3) / 4;
    int rb = (NHID + 255) / 256;
    dim3 gemm_grid(MPAD / 128, 2, 1);

    // ---- layer 0 ----
    aconv_kernel<<<(MPAD * 128 + 255) / 256, 256>>>(
        (const float4*)x_user, p_deg + 0 * N_SPOT, N_USER, 128, MPAD,
        (__nv_bfloat162*)p_Au2);
    hmma_gemm<0><<<gemm_grid, 256, SMEM>>>(
        p_Au2, 1024, p_B2 + WOFF_L0US, 1024, p_tmp_u, nullptr, nullptr,
        HID, N_USER, 512, 0, 0, 0);
    hmma_gemm<0><<<gemm_grid, 256, SMEM>>>(
        p_As2, 1024, p_B2 + WOFF_L0SU, 1024, p_tmp_s, nullptr, nullptr,
        HID, N_SPOT, 512, 0, 0, 0);
    // gathers emit both fp32 h and next layer's split-bf16 A operand
    gather_kernel<<<gb, 256>>>((const float4*)p_tmp_u, p_off_us, p_csr_us,
                               p_deg + 1 * N_SPOT, (float4*)p_hs, N_SPOT,
                               (__nv_bfloat162*)p_As2, p_deg + 2 * N_SPOT);
    gather_kernel<<<gb, 256>>>((const float4*)p_tmp_s, p_off_su, p_csr_su,
                               p_deg + 3 * N_SPOT, (float4*)p_hu, N_USER,
                               (__nv_bfloat162*)p_Au2, p_deg + 0 * N_SPOT);

    // ---- layers 1 & 2 ----
    for (int l = 1; l < 3; l++) {
        float* hs_new = p_hs + l * HN;
        float* hu_new = p_hu + l * HN;
        bool last = (l == 2);
        hmma_gemm<0><<<gemm_grid, 256, SMEM>>>(
            p_Au2, 512, p_B2 + WOFF_MUS + (l - 1) * 256 * 512, 512, p_tmp_u, nullptr, nullptr,
            HID, N_USER, 256, 0, 0, 0);
        hmma_gemm<0><<<gemm_grid, 256, SMEM>>>(
            p_As2, 512, p_B2 + WOFF_MSU + (l - 1) * 256 * 512, 512, p_tmp_s, nullptr, nullptr,
            HID, N_SPOT, 256, 0, 0, 0);
        gather_kernel<<<gb, 256>>>((const float4*)p_tmp_u, p_off_us, p_csr_us,
                                   p_deg + 1 * N_SPOT, (float4*)hs_new, N_SPOT,
                                   last ? nullptr : (__nv_bfloat162*)p_As2,
                                   last ? nullptr : p_deg + 2 * N_SPOT);
        gather_kernel<<<gb, 256>>>((const float4*)p_tmp_s, p_off_su, p_csr_su,
                                   p_deg + 3 * N_SPOT, (float4*)hu_new, N_USER,
                                   last ? nullptr : (__nv_bfloat162*)p_Au2,
                                   last ? nullptr : p_deg + 0 * N_SPOT);
    }

    // ---- outputs ----
    mean_kernel<<<rb, 256>>>(p_hs, p_hs + HN, p_hs + 2 * HN,
                             p_hu, p_hu + HN, p_hu + 2 * HN, out, NHID);
    out_head_kernel<<<(2 * N_SPOT * 32 + 255) / 256, 256>>>(
        p_hs + 2 * HN, p_hu + 2 * HN, W_out_s, b_out_s, W_out_u, b_out_u,
        out + 2 * (size_t)NHID, out + 2 * (size_t)NHID + N_SPOT);
}